// round 15
// baseline (speedup 1.0000x reference)
#include <cuda_runtime.h>
#include <cuda_bf16.h>
#include <math.h>
#include <stdint.h>

#define Hq 32
#define KVH 8
#define HD 128
#define Bn 4
#define Sn 1024
#define DM 4096
#define KVD 1024
#define NTOK (Bn*Sn)
#define WINDOW 512
#define NQKV (DM + 2*KVD)
#define KVLD (2*KVD)

#if defined(__CUDA_ARCH_FEAT_SM103_ALL) || defined(__CUDA_ARCH_FEAT_SM100_ALL)
#define TC_FEAT 1
#else
#define TC_FEAT 0
#endif

// Scratch
__device__ float g_q[NTOK * DM];
__device__ float g_kv[NTOK * KVLD];
__device__ __nv_bfloat16 g_a_hi[NTOK * DM];
__device__ __nv_bfloat16 g_a_lo[NTOK * DM];
__device__ __nv_bfloat16 g_wqkv_hi[NQKV * DM];
__device__ __nv_bfloat16 g_wqkv_lo[NQKV * DM];
__device__ __nv_bfloat16 g_wo_hi[DM * DM];
__device__ __nv_bfloat16 g_wo_lo[DM * DM];
__device__ __nv_bfloat16 g_qs_hi[NTOK * DM];
__device__ __nv_bfloat16 g_qs_lo[NTOK * DM];
__device__ __nv_bfloat16 g_ks_hi[NTOK * KVD];
__device__ __nv_bfloat16 g_ks_lo[NTOK * KVD];
__device__ __nv_bfloat16 g_vt_hi[NTOK * KVD];
__device__ __nv_bfloat16 g_vt_lo[NTOK * KVD];
__device__ __nv_bfloat16 g_o_hi[NTOK * DM];
__device__ __nv_bfloat16 g_o_lo[NTOK * DM];

__device__ __forceinline__ uint32_t smem_u32(const void* p) {
    uint32_t a;
    asm("{ .reg .u64 t; cvta.to.shared.u64 t, %1; cvt.u32.u64 %0, t; }"
        : "=r"(a) : "l"(p));
    return a;
}
__device__ __forceinline__ uint32_t elect_one() {
    uint32_t pred;
    asm volatile("{\n .reg .pred p;\n elect.sync _|p, 0xFFFFFFFF;\n"
                 " selp.b32 %0, 1, 0, p;\n}" : "=r"(pred));
    return pred;
}
#define SMEM_SW128(off) ((off) ^ (((off) >> 3) & 0x70))
static constexpr uint64_t DESC_BASE_SW128 =
    (uint64_t(2) << 61) | (uint64_t(1) << 46) | (uint64_t(64) << 32) |
    (uint64_t(1) << 16);
__device__ __forceinline__ uint64_t make_desc(uint32_t addr) {
    return DESC_BASE_SW128 | ((uint64_t)(addr >> 4) & 0x3FFF);
}
#define MBAR_INIT(a, n) \
    asm volatile("mbarrier.init.shared.b64 [%0], %1;" :: "r"(a), "r"(n) : "memory")
#define MBAR_INVAL(a) \
    asm volatile("mbarrier.inval.shared.b64 [%0];" :: "r"(a) : "memory")
__device__ __forceinline__ void mbar_wait(uint32_t mbar, uint32_t parity) {
    uint32_t done;
    asm volatile("{\n\t.reg .pred p;\n\t"
        "mbarrier.try_wait.parity.acquire.cta.shared::cta.b64 p, [%1], %2;\n\t"
        "selp.b32 %0, 1, 0, p;\n\t}" : "=r"(done) : "r"(mbar), "r"(parity) : "memory");
    while (!done) {
        asm volatile("{\n\t.reg .pred p;\n\t"
            "mbarrier.try_wait.parity.acquire.cta.shared::cta.b64 p, [%1], %2, 0x989680;\n\t"
            "selp.b32 %0, 1, 0, p;\n\t}" : "=r"(done) : "r"(mbar), "r"(parity) : "memory");
    }
}
#define CP_ASYNC16(dst, src) \
    asm volatile("cp.async.cg.shared.global [%0], [%1], 16;" :: "r"(dst), "l"(src))
#define CP_COMMIT() asm volatile("cp.async.commit_group;" ::: "memory")
#define CP_WAIT0()  asm volatile("cp.async.wait_group 0;" ::: "memory")
#define CP_WAIT1()  asm volatile("cp.async.wait_group 1;" ::: "memory")

#if TC_FEAT
__device__ __forceinline__ void mma_bf16_ss(
    uint32_t d_tmem, uint64_t a_desc, uint64_t b_desc, uint32_t idesc, bool acc)
{
    uint32_t en = acc ? 1u : 0u;
    asm volatile(
        "{\n\t.reg .pred p;\n\tsetp.ne.u32 p, %4, 0;\n\t"
        "tcgen05.mma.cta_group::1.kind::f16 [%0], %1, %2, %3, {%5,%5,%5,%5}, p;\n\t}"
        :: "r"(d_tmem), "l"(a_desc), "l"(b_desc), "r"(idesc), "r"(en), "r"(0u)
        : "memory");
}
#define TC_ALLOC(a, n) \
    asm volatile("tcgen05.alloc.cta_group::1.sync.aligned.shared::cta.b32 [%0], %1;" \
                 :: "r"(a), "r"((uint32_t)(n)) : "memory")
#define TC_DEALLOC(t, n) \
    asm volatile("tcgen05.dealloc.cta_group::1.sync.aligned.b32 %0, %1;" \
                 :: "r"(t), "r"((uint32_t)(n)))
#define TC_RELINQ() \
    asm volatile("tcgen05.relinquish_alloc_permit.cta_group::1.sync.aligned;")
#define TC_COMMIT(m) \
    asm volatile("tcgen05.commit.cta_group::1.mbarrier::arrive::one.shared::cluster.b64 [%0];" \
                 :: "r"(m) : "memory")
#define TC_FENCE_AFTER() asm volatile("tcgen05.fence::after_thread_sync;" ::: "memory")
#define FENCE_ASYNC_SHARED() asm volatile("fence.proxy.async.shared::cta;" ::: "memory")
#define TC_LD_X32(r, addr) \
    asm volatile("tcgen05.ld.sync.aligned.32x32b.x32.b32 " \
        "{%0,%1,%2,%3,%4,%5,%6,%7,%8,%9,%10,%11,%12,%13,%14,%15," \
        "%16,%17,%18,%19,%20,%21,%22,%23,%24,%25,%26,%27,%28,%29,%30,%31}, [%32];" \
        : "=r"((r)[0]), "=r"((r)[1]), "=r"((r)[2]), "=r"((r)[3]), \
          "=r"((r)[4]), "=r"((r)[5]), "=r"((r)[6]), "=r"((r)[7]), \
          "=r"((r)[8]), "=r"((r)[9]), "=r"((r)[10]), "=r"((r)[11]), \
          "=r"((r)[12]), "=r"((r)[13]), "=r"((r)[14]), "=r"((r)[15]), \
          "=r"((r)[16]), "=r"((r)[17]), "=r"((r)[18]), "=r"((r)[19]), \
          "=r"((r)[20]), "=r"((r)[21]), "=r"((r)[22]), "=r"((r)[23]), \
          "=r"((r)[24]), "=r"((r)[25]), "=r"((r)[26]), "=r"((r)[27]), \
          "=r"((r)[28]), "=r"((r)[29]), "=r"((r)[30]), "=r"((r)[31]) \
        : "r"(addr))
#define TC_WAIT_LD() asm volatile("tcgen05.wait::ld.sync.aligned;" ::: "memory")

__device__ __forceinline__ void split2(float a, float b, uint32_t& hw, uint32_t& lw) {
    __nv_bfloat16 ha = __float2bfloat16_rn(a);
    __nv_bfloat16 hb = __float2bfloat16_rn(b);
    __nv_bfloat16 la = __float2bfloat16_rn(a - __bfloat162float(ha));
    __nv_bfloat16 lb = __float2bfloat16_rn(b - __bfloat162float(hb));
    hw = ((uint32_t)__bfloat16_as_ushort(hb) << 16) | (uint32_t)__bfloat16_as_ushort(ha);
    lw = ((uint32_t)__bfloat16_as_ushort(lb) << 16) | (uint32_t)__bfloat16_as_ushort(la);
}
#endif

// ---------------------------------------------------------------------------
// tcgen05 GEMM: M=128 x N=256 tile, K-tile 32, 2 stages, 2 CTAs/SM.
// A stage 16KB (128 rows), B stage 32KB (256 rows). TMEM = 256 cols/CTA.
// Cross-CTA overlap hides per-tile sync/stage overhead.
// ---------------------------------------------------------------------------
#define G_OFF_B   16384
#define G_STAGE   49152                  // 16KB A + 32KB B
#define G_MBAR    (2 * G_STAGE)          // 2 x 8B MMA mbars
#define G_TPTR    (2 * G_STAGE + 32)
#define G_DYN     (2 * G_STAGE + 64 + 1024)
#define G_IDESC   ((1u<<4)|(1u<<7)|(1u<<10)|(32u<<17)|(8u<<24))   // M=128, N=256

__global__ __launch_bounds__(256, 2) void tc_gemm(
    const __nv_bfloat16* __restrict__ Ahi, const __nv_bfloat16* __restrict__ Alo,
    const __nv_bfloat16* __restrict__ Bhi, const __nv_bfloat16* __restrict__ Blo,
    float* __restrict__ C, float* __restrict__ C2,
    int ldc, int ldc2, int nsplit, int K)
{
#if TC_FEAT
    extern __shared__ char dsm[];
    char* smb = (char*)(((uintptr_t)dsm + 1023) & ~(uintptr_t)1023);
    const uint32_t smb_u = smem_u32(smb);
    const int tid = threadIdx.x;
    const int wid = tid >> 5;
    const int lane = tid & 31;
    const int m0 = blockIdx.y * 128;
    const int n0 = blockIdx.x * 256;

    if (wid == 0) TC_ALLOC(smb_u + G_TPTR, 256);
    if (tid == 0) {
        MBAR_INIT(smb_u + G_MBAR + 0, 1);
        MBAR_INIT(smb_u + G_MBAR + 8, 1);
    }
    __syncthreads();
    uint32_t tmem;
    asm volatile("ld.shared.b32 %0, [%1];" : "=r"(tmem) : "r"(smb_u + G_TPTR));

    const int T = K >> 5;
    auto stage = [&](int t) {
        const uint32_t sbase = smb_u + (t & 1) * G_STAGE;
        const int k0 = t * 32;
#pragma unroll
        for (int r = 0; r < 4; ++r) {          // A: 128 rows x [hi|lo] 128B
            int i = tid + r * 256;
            int row = i >> 3, c = i & 7;
            uint32_t dst = sbase + SMEM_SW128((uint32_t)(row * 128 + c * 16));
            const __nv_bfloat16* src = ((c & 4) ? Alo : Ahi)
                + (size_t)(m0 + row) * K + k0 + (c & 3) * 8;
            CP_ASYNC16(dst, src);
        }
#pragma unroll
        for (int r = 0; r < 8; ++r) {          // B: 256 rows x [hi|lo] 128B
            int i = tid + r * 256;
            int row = i >> 3, c = i & 7;
            uint32_t dst = sbase + G_OFF_B + SMEM_SW128((uint32_t)(row * 128 + c * 16));
            const __nv_bfloat16* src = ((c & 4) ? Blo : Bhi)
                + (size_t)(n0 + row) * K + k0 + (c & 3) * 8;
            CP_ASYNC16(dst, src);
        }
        CP_COMMIT();
    };

    stage(0);
    for (int t = 0; t < T; ++t) {
        if (t + 1 < T) {
            // buffer (t+1)&1 was consumed by MMA(t-1); wait its commit
            if (t >= 1)
                mbar_wait(smb_u + G_MBAR + 8 * ((t + 1) & 1),
                          (uint32_t)(((t - 1) / 2) & 1));
            stage(t + 1);
            CP_WAIT1();
        } else {
            CP_WAIT0();
        }
        FENCE_ASYNC_SHARED();
        __syncthreads();

        if (wid == 0 && elect_one()) {
            const uint32_t sbase = smb_u + (t & 1) * G_STAGE;
            uint64_t da = make_desc(sbase);
            uint64_t db = make_desc(sbase + G_OFF_B);
#pragma unroll
            for (int k = 0; k < 2; ++k) {
                bool first = (t == 0) && (k == 0);
                mma_bf16_ss(tmem, da + k * 2,     db + k * 2,     G_IDESC, !first);
                mma_bf16_ss(tmem, da + k * 2,     db + 4 + k * 2, G_IDESC, true);
                mma_bf16_ss(tmem, da + 4 + k * 2, db + k * 2,     G_IDESC, true);
            }
            TC_COMMIT(smb_u + G_MBAR + 8 * (t & 1));
        }
    }
#pragma unroll
    for (int i = 0; i < 2; ++i) {
        int cnt = (T - i + 1) / 2;
        if (cnt > 0) mbar_wait(smb_u + G_MBAR + 8 * i, (uint32_t)((cnt - 1) & 1));
    }
    TC_FENCE_AFTER();

    // epilogue: warp w -> rows (w&3)*32+lane, cols (w>>2)*128 .. +127
    {
        const int sub = wid & 3;
        const int chalf = wid >> 2;
        const int grow = m0 + sub * 32 + lane;
        float* base;
        int col, ld;
        if (n0 < nsplit) { base = C;  col = n0;          ld = ldc;  }
        else             { base = C2; col = n0 - nsplit; ld = ldc2; }
        float* crow = base + (size_t)grow * ld + col + chalf * 128;
        uint32_t regs[32];
#pragma unroll
        for (int c = 0; c < 4; ++c) {
            TC_LD_X32(regs, tmem + chalf * 128 + c * 32);
            TC_WAIT_LD();
#pragma unroll
            for (int i = 0; i < 8; ++i)
                *(float4*)(crow + c * 32 + 4 * i) = make_float4(
                    __uint_as_float(regs[4*i]), __uint_as_float(regs[4*i+1]),
                    __uint_as_float(regs[4*i+2]), __uint_as_float(regs[4*i+3]));
        }
    }
    __syncthreads();
    if (tid == 0) {
        MBAR_INVAL(smb_u + G_MBAR + 0);
        MBAR_INVAL(smb_u + G_MBAR + 8);
    }
    __syncthreads();
    if (wid == 0) { TC_RELINQ(); TC_DEALLOC(tmem, 256); }
#endif
}

// ---------------------------------------------------------------------------
// tcgen05 attention (byte-identical to the 970us version).
// ---------------------------------------------------------------------------
#define AT_Q     0
#define AT_KP    131072
#define AT_V     196608
#define AT_MBAR  229376
#define AT_TPTR  229408
#define AT_DYN   (229440 + 1024)
#define IDESC_S  ((1u<<4)|(1u<<7)|(1u<<10)|(8u<<17)|(8u<<24))
#define IDESC_O  ((1u<<4)|(1u<<7)|(1u<<10)|(16u<<17)|(8u<<24))
#define SMAX_C   12.0f

__global__ __launch_bounds__(256, 1) void tc_attn(
    const __nv_bfloat16* __restrict__ qsh, const __nv_bfloat16* __restrict__ qsl,
    const __nv_bfloat16* __restrict__ ksh, const __nv_bfloat16* __restrict__ ksl,
    const __nv_bfloat16* __restrict__ vth, const __nv_bfloat16* __restrict__ vtl,
    __nv_bfloat16* __restrict__ ohi, __nv_bfloat16* __restrict__ olo)
{
#if TC_FEAT
    extern __shared__ char dsm[];
    char* smb = (char*)(((uintptr_t)dsm + 1023) & ~(uintptr_t)1023);
    const uint32_t smb_u = smem_u32(smb);
    const uint32_t mbar_s = smb_u + AT_MBAR;
    const uint32_t mbar_o = smb_u + AT_MBAR + 8;
    const int tid = threadIdx.x;
    const int wid = tid >> 5;
    const int q0 = (int)(gridDim.x - 1 - blockIdx.x) * 64;
    const int kvh = blockIdx.y;
    const int b = blockIdx.z;
    const int bk = b * KVH + kvh;

    if (wid == 0) TC_ALLOC(smb_u + AT_TPTR, 512);
    if (tid == 0) { MBAR_INIT(mbar_s, 1); MBAR_INIT(mbar_o, 1); }
    __syncthreads();
    uint32_t tmem;
    asm volatile("ld.shared.b32 %0, [%1];" : "=r"(tmem) : "r"(smb_u + AT_TPTR));
    const uint32_t tmS = tmem;
    const uint32_t tmO = tmem + 128;

#pragma unroll
    for (int r = 0; r < 32; ++r) {
        int u = tid + r * 256;
        int row = u >> 5, cc = u & 31;
        int s = cc >> 4, hh = (cc >> 3) & 1, c = cc & 7;
        uint32_t byte = (uint32_t)(((row >> 3) + (s * 2 + hh) * 32) * 1024 +
                                   (row & 7) * 128 + c * 16);
        int tok = b * Sn + q0 + (row & 63);
        int head = kvh * 4 + (row >> 6);
        const __nv_bfloat16* src = (s ? qsl : qsh)
            + (size_t)tok * DM + head * HD + hh * 64 + c * 8;
        CP_ASYNC16(smb_u + AT_Q + SMEM_SW128(byte), src);
    }
    CP_COMMIT();

    const int kc0 = (q0 >= WINDOW) ? (q0 - WINDOW) : 0;
    const int nch = (q0 - kc0) / 64 + 1;
    float l_i = 0.f;
    uint32_t ps = 0, po = 0;
    const int atom = wid >> 2;
    const int grow = tid;
    const int qi = q0 + (grow & 63);

    for (int ci = 0; ci < nch; ++ci) {
        const int kc = kc0 + ci * 64;
        if (ci > 0) { mbar_wait(mbar_o, po); po ^= 1; }

#pragma unroll
        for (int r = 0; r < 8; ++r) {
            int u = tid + r * 256;
            int key = u >> 5, cc = u & 31;
            int s = cc >> 4, hh = (cc >> 3) & 1, c = cc & 7;
            uint32_t byte = (uint32_t)(((key >> 3) + (s * 2 + hh) * 8) * 1024 +
                                       (key & 7) * 128 + c * 16);
            const __nv_bfloat16* src = (s ? ksl : ksh)
                + (size_t)(b * Sn + kc + key) * KVD + kvh * HD + hh * 64 + c * 8;
            CP_ASYNC16(smb_u + AT_KP + SMEM_SW128(byte), src);
        }
        CP_COMMIT();
#pragma unroll
        for (int r = 0; r < 8; ++r) {
            int u = tid + r * 256;
            int d = u >> 4, cc = u & 15;
            int s = cc >> 3, c = cc & 7;
            uint32_t byte = (uint32_t)(((d >> 3) + s * 16) * 1024 +
                                       (d & 7) * 128 + c * 16);
            const __nv_bfloat16* src = (s ? vtl : vth)
                + (size_t)bk * HD * Sn + (size_t)d * Sn + kc + c * 8;
            CP_ASYNC16(smb_u + AT_V + SMEM_SW128(byte), src);
        }
        CP_COMMIT();
        CP_WAIT1();
        FENCE_ASYNC_SHARED();
        __syncthreads();

        if (wid == 0 && elect_one()) {
            uint64_t dq = make_desc(smb_u + AT_Q);
            uint64_t dk = make_desc(smb_u + AT_KP);
#pragma unroll
            for (int m = 0; m < 2; ++m)
#pragma unroll
                for (int pat = 0; pat < 3; ++pat) {
                    int sa = (pat == 2), sb = (pat == 1);
#pragma unroll
                    for (int k = 0; k < 8; ++k) {
                        uint64_t qo = (uint64_t)(m * 1024 +
                                      (sa * 2 + (k >> 2)) * 2048 + (k & 3) * 2);
                        uint64_t ko = (uint64_t)((sb * 2 + (k >> 2)) * 512 + (k & 3) * 2);
                        mma_bf16_ss(tmS + m * 64, dq + qo, dk + ko, IDESC_S,
                                    !(pat == 0 && k == 0));
                    }
                }
            TC_COMMIT(mbar_s);
        }

        mbar_wait(mbar_s, ps);
        ps ^= 1;
        TC_FENCE_AFTER();
        uint32_t su[64];
        TC_LD_X32(su, tmS + atom * 64);
        TC_LD_X32(su + 32, tmS + atom * 64 + 32);
        TC_WAIT_LD();
        float l_add = 0.f;
#pragma unroll
        for (int c16 = 0; c16 < 8; ++c16) {
            uint32_t wh[4], wl[4];
#pragma unroll
            for (int e = 0; e < 4; ++e) {
                int i0 = c16 * 8 + e * 2;
                int j0 = kc + i0;
                float s0 = __uint_as_float(su[i0]);
                float s1 = __uint_as_float(su[i0 + 1]);
                float p0 = ((j0 <= qi) && (j0 > qi - WINDOW)) ? __expf(s0 - SMAX_C) : 0.f;
                float p1 = ((j0+1 <= qi) && (j0+1 > qi - WINDOW)) ? __expf(s1 - SMAX_C) : 0.f;
                l_add += p0 + p1;
                split2(p0, p1, wh[e], wl[e]);
            }
            uint32_t bh = (uint32_t)((grow >> 3) * 1024 + (grow & 7) * 128 + c16 * 16);
            uint32_t bl = bh + 32 * 1024;
            *(uint4*)(smb + AT_KP + SMEM_SW128(bh)) = make_uint4(wh[0], wh[1], wh[2], wh[3]);
            *(uint4*)(smb + AT_KP + SMEM_SW128(bl)) = make_uint4(wl[0], wl[1], wl[2], wl[3]);
        }
        l_i += l_add;
        CP_WAIT0();
        FENCE_ASYNC_SHARED();
        __syncthreads();

        if (wid == 0 && elect_one()) {
            uint64_t dp = make_desc(smb_u + AT_KP);
            uint64_t dv = make_desc(smb_u + AT_V);
#pragma unroll
            for (int m = 0; m < 2; ++m)
#pragma unroll
                for (int pat = 0; pat < 3; ++pat) {
                    int sp = (pat == 2), sv = (pat == 1);
#pragma unroll
                    for (int k = 0; k < 4; ++k) {
                        uint64_t pofs = (uint64_t)(m * 1024 + sp * 2048 + k * 2);
                        uint64_t vofs = (uint64_t)(sv * 1024 + k * 2);
                        mma_bf16_ss(tmO + m * 128, dp + pofs, dv + vofs, IDESC_O,
                                    !(ci == 0 && pat == 0 && k == 0));
                    }
                }
            TC_COMMIT(mbar_o);
        }
        __syncthreads();
    }

    mbar_wait(mbar_o, po);
    TC_FENCE_AFTER();

    {
        const float inv = 1.0f / l_i;
        const int tok = b * Sn + q0 + (grow & 63);
        const int head = kvh * 4 + (grow >> 6);
        __nv_bfloat16* bh = ohi + (size_t)tok * DM + head * HD;
        __nv_bfloat16* bl = olo + (size_t)tok * DM + head * HD;
#pragma unroll
        for (int c = 0; c < 4; ++c) {
            uint32_t ov[32];
            TC_LD_X32(ov, tmO + atom * 128 + c * 32);
            TC_WAIT_LD();
#pragma unroll
            for (int g = 0; g < 4; ++g) {
                uint32_t ph[4], pl[4];
#pragma unroll
                for (int e = 0; e < 4; ++e) {
                    float v0 = __uint_as_float(ov[g*8 + e*2]) * inv;
                    float v1 = __uint_as_float(ov[g*8 + e*2 + 1]) * inv;
                    split2(v0, v1, ph[e], pl[e]);
                }
                *(uint4*)(bh + c * 32 + g * 8) = make_uint4(ph[0], ph[1], ph[2], ph[3]);
                *(uint4*)(bl + c * 32 + g * 8) = make_uint4(pl[0], pl[1], pl[2], pl[3]);
            }
        }
    }
    __syncthreads();
    if (tid == 0) { MBAR_INVAL(mbar_s); MBAR_INVAL(mbar_o); }
    __syncthreads();
    if (wid == 0) { TC_RELINQ(); TC_DEALLOC(tmem, 512); }
#endif
}

// ---------------------------------------------------------------------------
// Pre-pass kernels (unchanged)
// ---------------------------------------------------------------------------
__global__ __launch_bounds__(256) void convert_split(
    const float* __restrict__ x, __nv_bfloat16* __restrict__ hi,
    __nv_bfloat16* __restrict__ lo, int n4)
{
    int i = blockIdx.x * 256 + threadIdx.x;
    if (i >= n4) return;
    float4 v = ((const float4*)x)[i];
    __nv_bfloat16 h[4], l[4];
    float vv[4] = {v.x, v.y, v.z, v.w};
#pragma unroll
    for (int j = 0; j < 4; ++j) {
        h[j] = __float2bfloat16_rn(vv[j]);
        l[j] = __float2bfloat16_rn(vv[j] - __bfloat162float(h[j]));
    }
    ((uint64_t*)hi)[i] = *(uint64_t*)h;
    ((uint64_t*)lo)[i] = *(uint64_t*)l;
}

__global__ __launch_bounds__(256) void transpose_split(
    const float* __restrict__ W, __nv_bfloat16* __restrict__ Thi,
    __nv_bfloat16* __restrict__ Tlo, int K, int N, int noff)
{
    __shared__ float tile[32][33];
    const int n0 = blockIdx.x * 32, k0 = blockIdx.y * 32;
    const int tx = threadIdx.x, ty = threadIdx.y;
#pragma unroll
    for (int i = 0; i < 32; i += 8)
        tile[ty + i][tx] = W[(size_t)(k0 + ty + i) * N + n0 + tx];
    __syncthreads();
#pragma unroll
    for (int i = 0; i < 32; i += 8) {
        float v = tile[tx][ty + i];
        __nv_bfloat16 h = __float2bfloat16_rn(v);
        size_t idx = (size_t)(noff + n0 + ty + i) * K + k0 + tx;
        Thi[idx] = h;
        Tlo[idx] = __float2bfloat16_rn(v - __bfloat162float(h));
    }
}

__global__ __launch_bounds__(256) void v_split_t(
    const float* __restrict__ kv, __nv_bfloat16* __restrict__ vth,
    __nv_bfloat16* __restrict__ vtl)
{
    __shared__ float tile[32][33];
    const int t0 = blockIdx.x * 32, d0 = blockIdx.y * 32;
    const int bkk = blockIdx.z;
    const int bb = bkk >> 3, kvh = bkk & 7;
    const int tx = threadIdx.x, ty = threadIdx.y;
#pragma unroll
    for (int i = 0; i < 32; i += 8)
        tile[ty + i][tx] = kv[(size_t)(bb * Sn + t0 + ty + i) * KVLD +
                              KVD + kvh * HD + d0 + tx];
    __syncthreads();
#pragma unroll
    for (int i = 0; i < 32; i += 8) {
        float x = tile[tx][ty + i];
        __nv_bfloat16 h = __float2bfloat16_rn(x);
        size_t idx = (size_t)bkk * HD * Sn + (size_t)(d0 + ty + i) * Sn + t0 + tx;
        vth[idx] = h;
        vtl[idx] = __float2bfloat16_rn(x - __bfloat162float(h));
    }
}

__global__ __launch_bounds__(256) void rope_split(
    const float* __restrict__ q, const float* __restrict__ kv,
    __nv_bfloat16* __restrict__ qsh, __nv_bfloat16* __restrict__ qsl,
    __nv_bfloat16* __restrict__ ksh, __nv_bfloat16* __restrict__ ksl,
    const int* __restrict__ pos_ids)
{
    const int tok = blockIdx.x;
    __shared__ float cs[64], sn[64];
    const int tid = threadIdx.x;
    const float pos = (float)pos_ids[tok];
    const float SCALE = 0.08838834764831845f;
    if (tid < 64) {
        float inv = powf(1.0e6f, -((float)tid) / 64.0f);
        sincosf(pos * inv, &sn[tid], &cs[tid]);
    }
    __syncthreads();
    for (int p = tid; p < (Hq + KVH) * 64; p += 256) {
        int head = p >> 6, i = p & 63;
        float c = cs[i], s = sn[i];
        if (head < Hq) {
            size_t base = (size_t)tok * DM + head * HD;
            float x1 = q[base + i], x2 = q[base + i + 64];
            float y1 = (x1 * c - x2 * s) * SCALE;
            float y2 = (x2 * c + x1 * s) * SCALE;
            __nv_bfloat16 h1 = __float2bfloat16_rn(y1);
            __nv_bfloat16 h2 = __float2bfloat16_rn(y2);
            qsh[base + i] = h1;
            qsh[base + i + 64] = h2;
            qsl[base + i] = __float2bfloat16_rn(y1 - __bfloat162float(h1));
            qsl[base + i + 64] = __float2bfloat16_rn(y2 - __bfloat162float(h2));
        } else {
            int kh = head - Hq;
            size_t sbase = (size_t)tok * KVLD + kh * HD;
            size_t dbase = (size_t)tok * KVD + kh * HD;
            float x1 = kv[sbase + i], x2 = kv[sbase + i + 64];
            float y1 = x1 * c - x2 * s;
            float y2 = x2 * c + x1 * s;
            __nv_bfloat16 h1 = __float2bfloat16_rn(y1);
            __nv_bfloat16 h2 = __float2bfloat16_rn(y2);
            ksh[dbase + i] = h1;
            ksh[dbase + i + 64] = h2;
            ksl[dbase + i] = __float2bfloat16_rn(y1 - __bfloat162float(h1));
            ksl[dbase + i + 64] = __float2bfloat16_rn(y2 - __bfloat162float(h2));
        }
    }
}

// ---------------------------------------------------------------------------
extern "C" void kernel_launch(void* const* d_in, const int* in_sizes, int n_in,
                              void* d_out, int out_size)
{
    const float* hidden = (const float*)d_in[0];
    const float* Wq = (const float*)d_in[1];
    const float* Wk = (const float*)d_in[2];
    const float* Wv = (const float*)d_in[3];
    const float* Wo = (const float*)d_in[4];
    const int* pos_ids = (const int*)d_in[8];
    float* out = (float*)d_out;

    float *qp, *kvp;
    __nv_bfloat16 *ahi, *alo, *wqkvh, *wqkvl, *woh, *wol;
    __nv_bfloat16 *qsh, *qsl, *ksh, *ksl, *vth, *vtl, *oh, *ol;
    cudaGetSymbolAddress((void**)&qp, g_q);
    cudaGetSymbolAddress((void**)&kvp, g_kv);
    cudaGetSymbolAddress((void**)&ahi, g_a_hi);
    cudaGetSymbolAddress((void**)&alo, g_a_lo);
    cudaGetSymbolAddress((void**)&wqkvh, g_wqkv_hi);
    cudaGetSymbolAddress((void**)&wqkvl, g_wqkv_lo);
    cudaGetSymbolAddress((void**)&woh, g_wo_hi);
    cudaGetSymbolAddress((void**)&wol, g_wo_lo);
    cudaGetSymbolAddress((void**)&qsh, g_qs_hi);
    cudaGetSymbolAddress((void**)&qsl, g_qs_lo);
    cudaGetSymbolAddress((void**)&ksh, g_ks_hi);
    cudaGetSymbolAddress((void**)&ksl, g_ks_lo);
    cudaGetSymbolAddress((void**)&vth, g_vt_hi);
    cudaGetSymbolAddress((void**)&vtl, g_vt_lo);
    cudaGetSymbolAddress((void**)&oh, g_o_hi);
    cudaGetSymbolAddress((void**)&ol, g_o_lo);

    cudaFuncSetAttribute(tc_gemm, cudaFuncAttributeMaxDynamicSharedMemorySize, G_DYN);
    cudaFuncSetAttribute(tc_attn, cudaFuncAttributeMaxDynamicSharedMemorySize, AT_DYN);

    // pre-pass
    convert_split<<<(NTOK * DM / 4) / 256, 256>>>(hidden, ahi, alo, NTOK * DM / 4);
    transpose_split<<<dim3(DM / 32, DM / 32), dim3(32, 8)>>>(Wq, wqkvh, wqkvl, DM, DM, 0);
    transpose_split<<<dim3(KVD / 32, DM / 32), dim3(32, 8)>>>(Wk, wqkvh, wqkvl, DM, KVD, DM);
    transpose_split<<<dim3(KVD / 32, DM / 32), dim3(32, 8)>>>(Wv, wqkvh, wqkvl, DM, KVD, DM + KVD);
    transpose_split<<<dim3(DM / 32, DM / 32), dim3(32, 8)>>>(Wo, woh, wol, DM, DM, 0);

    // merged QKV projection: N=6144, M-tiles of 128 (768 CTAs, 2/SM)
    tc_gemm<<<dim3(NQKV / 256, NTOK / 128), 256, G_DYN>>>(
        ahi, alo, wqkvh, wqkvl, qp, kvp, DM, KVLD, DM, DM);

    // rope + attention operand prep
    rope_split<<<NTOK, 256>>>(qp, kvp, qsh, qsl, ksh, ksl, pos_ids);
    v_split_t<<<dim3(Sn / 32, HD / 32, Bn * KVH), dim3(32, 8)>>>(kvp, vth, vtl);

    // attention
    tc_attn<<<dim3(Sn / 64, KVH, Bn), 256, AT_DYN>>>(
        qsh, qsl, ksh, ksl, vth, vtl, oh, ol);

    // output projection (512 CTAs, 2/SM)
    tc_gemm<<<dim3(DM / 256, NTOK / 128), 256, G_DYN>>>(
        oh, ol, woh, wol, out, out, DM, DM, DM, DM);
}

// round 16
// speedup vs baseline: 1.6134x; 1.6134x over previous
#include <cuda_runtime.h>
#include <cuda_bf16.h>
#include <math.h>
#include <stdint.h>

#define Hq 32
#define KVH 8
#define HD 128
#define Bn 4
#define Sn 1024
#define DM 4096
#define KVD 1024
#define NTOK (Bn*Sn)
#define WINDOW 512
#define NQKV (DM + 2*KVD)    // 6144
#define KVLD (2*KVD)         // 2048

#if defined(__CUDA_ARCH_FEAT_SM103_ALL) || defined(__CUDA_ARCH_FEAT_SM100_ALL)
#define TC_FEAT 1
#else
#define TC_FEAT 0
#endif

// Scratch
__device__ float g_q[NTOK * DM];
__device__ float g_kv[NTOK * KVLD];               // [tok][K 0..1023 | V 1024..2047]
__device__ __nv_bfloat16 g_a_hi[NTOK * DM];
__device__ __nv_bfloat16 g_a_lo[NTOK * DM];
__device__ __nv_bfloat16 g_wqkv_hi[NQKV * DM];    // rows: Wq^T | Wk^T | Wv^T (K-major)
__device__ __nv_bfloat16 g_wqkv_lo[NQKV * DM];
__device__ __nv_bfloat16 g_wo_hi[DM * DM];
__device__ __nv_bfloat16 g_wo_lo[DM * DM];
__device__ __nv_bfloat16 g_qs_hi[NTOK * DM];
__device__ __nv_bfloat16 g_qs_lo[NTOK * DM];
__device__ __nv_bfloat16 g_ks_hi[NTOK * KVD];
__device__ __nv_bfloat16 g_ks_lo[NTOK * KVD];
__device__ __nv_bfloat16 g_vt_hi[NTOK * KVD];
__device__ __nv_bfloat16 g_vt_lo[NTOK * KVD];
__device__ __nv_bfloat16 g_o_hi[NTOK * DM];
__device__ __nv_bfloat16 g_o_lo[NTOK * DM];

__device__ __forceinline__ uint32_t smem_u32(const void* p) {
    uint32_t a;
    asm("{ .reg .u64 t; cvta.to.shared.u64 t, %1; cvt.u32.u64 %0, t; }"
        : "=r"(a) : "l"(p));
    return a;
}
__device__ __forceinline__ uint32_t elect_one() {
    uint32_t pred;
    asm volatile("{\n .reg .pred p;\n elect.sync _|p, 0xFFFFFFFF;\n"
                 " selp.b32 %0, 1, 0, p;\n}" : "=r"(pred));
    return pred;
}
#define SMEM_SW128(off) ((off) ^ (((off) >> 3) & 0x70))
static constexpr uint64_t DESC_BASE_SW128 =
    (uint64_t(2) << 61) | (uint64_t(1) << 46) | (uint64_t(64) << 32) |
    (uint64_t(1) << 16);
__device__ __forceinline__ uint64_t make_desc(uint32_t addr) {
    return DESC_BASE_SW128 | ((uint64_t)(addr >> 4) & 0x3FFF);
}
#define MBAR_INIT(a, n) \
    asm volatile("mbarrier.init.shared.b64 [%0], %1;" :: "r"(a), "r"(n) : "memory")
#define MBAR_INVAL(a) \
    asm volatile("mbarrier.inval.shared.b64 [%0];" :: "r"(a) : "memory")
__device__ __forceinline__ void mbar_wait(uint32_t mbar, uint32_t parity) {
    uint32_t done;
    asm volatile("{\n\t.reg .pred p;\n\t"
        "mbarrier.try_wait.parity.acquire.cta.shared::cta.b64 p, [%1], %2;\n\t"
        "selp.b32 %0, 1, 0, p;\n\t}" : "=r"(done) : "r"(mbar), "r"(parity) : "memory");
    while (!done) {
        asm volatile("{\n\t.reg .pred p;\n\t"
            "mbarrier.try_wait.parity.acquire.cta.shared::cta.b64 p, [%1], %2, 0x989680;\n\t"
            "selp.b32 %0, 1, 0, p;\n\t}" : "=r"(done) : "r"(mbar), "r"(parity) : "memory");
    }
}
#define CP_ASYNC16(dst, src) \
    asm volatile("cp.async.cg.shared.global [%0], [%1], 16;" :: "r"(dst), "l"(src))
#define CP_COMMIT() asm volatile("cp.async.commit_group;" ::: "memory")
#define CP_WAIT0()  asm volatile("cp.async.wait_group 0;" ::: "memory")
#define CP_WAIT1()  asm volatile("cp.async.wait_group 1;" ::: "memory")

#if TC_FEAT
__device__ __forceinline__ void mma_bf16_ss(
    uint32_t d_tmem, uint64_t a_desc, uint64_t b_desc, uint32_t idesc, bool acc)
{
    uint32_t en = acc ? 1u : 0u;
    asm volatile(
        "{\n\t.reg .pred p;\n\tsetp.ne.u32 p, %4, 0;\n\t"
        "tcgen05.mma.cta_group::1.kind::f16 [%0], %1, %2, %3, {%5,%5,%5,%5}, p;\n\t}"
        :: "r"(d_tmem), "l"(a_desc), "l"(b_desc), "r"(idesc), "r"(en), "r"(0u)
        : "memory");
}
#define TC_ALLOC(a, n) \
    asm volatile("tcgen05.alloc.cta_group::1.sync.aligned.shared::cta.b32 [%0], %1;" \
                 :: "r"(a), "r"((uint32_t)(n)) : "memory")
#define TC_DEALLOC(t, n) \
    asm volatile("tcgen05.dealloc.cta_group::1.sync.aligned.b32 %0, %1;" \
                 :: "r"(t), "r"((uint32_t)(n)))
#define TC_RELINQ() \
    asm volatile("tcgen05.relinquish_alloc_permit.cta_group::1.sync.aligned;")
#define TC_COMMIT(m) \
    asm volatile("tcgen05.commit.cta_group::1.mbarrier::arrive::one.shared::cluster.b64 [%0];" \
                 :: "r"(m) : "memory")
#define TC_FENCE_AFTER() asm volatile("tcgen05.fence::after_thread_sync;" ::: "memory")
#define FENCE_ASYNC_SHARED() asm volatile("fence.proxy.async.shared::cta;" ::: "memory")
#define TC_LD_X32(r, addr) \
    asm volatile("tcgen05.ld.sync.aligned.32x32b.x32.b32 " \
        "{%0,%1,%2,%3,%4,%5,%6,%7,%8,%9,%10,%11,%12,%13,%14,%15," \
        "%16,%17,%18,%19,%20,%21,%22,%23,%24,%25,%26,%27,%28,%29,%30,%31}, [%32];" \
        : "=r"((r)[0]), "=r"((r)[1]), "=r"((r)[2]), "=r"((r)[3]), \
          "=r"((r)[4]), "=r"((r)[5]), "=r"((r)[6]), "=r"((r)[7]), \
          "=r"((r)[8]), "=r"((r)[9]), "=r"((r)[10]), "=r"((r)[11]), \
          "=r"((r)[12]), "=r"((r)[13]), "=r"((r)[14]), "=r"((r)[15]), \
          "=r"((r)[16]), "=r"((r)[17]), "=r"((r)[18]), "=r"((r)[19]), \
          "=r"((r)[20]), "=r"((r)[21]), "=r"((r)[22]), "=r"((r)[23]), \
          "=r"((r)[24]), "=r"((r)[25]), "=r"((r)[26]), "=r"((r)[27]), \
          "=r"((r)[28]), "=r"((r)[29]), "=r"((r)[30]), "=r"((r)[31]) \
        : "r"(addr))
#define TC_WAIT_LD() asm volatile("tcgen05.wait::ld.sync.aligned;" ::: "memory")

__device__ __forceinline__ void split2(float a, float b, uint32_t& hw, uint32_t& lw) {
    __nv_bfloat16 ha = __float2bfloat16_rn(a);
    __nv_bfloat16 hb = __float2bfloat16_rn(b);
    __nv_bfloat16 la = __float2bfloat16_rn(a - __bfloat162float(ha));
    __nv_bfloat16 lb = __float2bfloat16_rn(b - __bfloat162float(hb));
    hw = ((uint32_t)__bfloat16_as_ushort(hb) << 16) | (uint32_t)__bfloat16_as_ushort(ha);
    lw = ((uint32_t)__bfloat16_as_ushort(lb) << 16) | (uint32_t)__bfloat16_as_ushort(la);
}
#endif

// ---------------------------------------------------------------------------
// tcgen05 GEMM (R8/R13-proven): 256x256 tile, K-tile 32, 3-stage cp.async,
// MMA-first ordering. Output: n0 < nsplit -> C (ldc), else C2 (ldc2).
// Epilogue batches 2 TMEM loads per wait.
// ---------------------------------------------------------------------------
#define TCG_OFF_B 32768
#define G_STAGE   65536
#define G_MBAR    (3 * G_STAGE)
#define G_TPTR    (3 * G_STAGE + 32)
#define G_DYN     (3 * G_STAGE + 64 + 1024)
#define G_IDESC   ((1u<<4)|(1u<<7)|(1u<<10)|(32u<<17)|(8u<<24))   // N=256

__global__ __launch_bounds__(256, 1) void tc_gemm(
    const __nv_bfloat16* __restrict__ Ahi, const __nv_bfloat16* __restrict__ Alo,
    const __nv_bfloat16* __restrict__ Bhi, const __nv_bfloat16* __restrict__ Blo,
    float* __restrict__ C, float* __restrict__ C2,
    int ldc, int ldc2, int nsplit, int K)
{
#if TC_FEAT
    extern __shared__ char dsm[];
    char* smb = (char*)(((uintptr_t)dsm + 1023) & ~(uintptr_t)1023);
    const uint32_t smb_u = smem_u32(smb);
    const int tid = threadIdx.x;
    const int wid = tid >> 5;
    const int lane = tid & 31;
    const int m0 = blockIdx.y * 256;
    const int n0 = blockIdx.x * 256;

    if (wid == 0) TC_ALLOC(smb_u + G_TPTR, 512);
    if (tid == 0) {
        MBAR_INIT(smb_u + G_MBAR + 0, 1);
        MBAR_INIT(smb_u + G_MBAR + 8, 1);
        MBAR_INIT(smb_u + G_MBAR + 16, 1);
    }
    __syncthreads();
    uint32_t tmem;
    asm volatile("ld.shared.b32 %0, [%1];" : "=r"(tmem) : "r"(smb_u + G_TPTR));

    const int T = K >> 5;
    auto stage = [&](int t) {
        const uint32_t sbase = smb_u + (t % 3) * G_STAGE;
        const int k0 = t * 32;
#pragma unroll
        for (int r = 0; r < 8; ++r) {
            int i = tid + r * 256;
            int row = i >> 3, c = i & 7;
            uint32_t dst = sbase + SMEM_SW128((uint32_t)(row * 128 + c * 16));
            const __nv_bfloat16* src = ((c & 4) ? Alo : Ahi)
                + (size_t)(m0 + row) * K + k0 + (c & 3) * 8;
            CP_ASYNC16(dst, src);
        }
#pragma unroll
        for (int r = 0; r < 8; ++r) {
            int i = tid + r * 256;
            int row = i >> 3, c = i & 7;
            uint32_t dst = sbase + TCG_OFF_B + SMEM_SW128((uint32_t)(row * 128 + c * 16));
            const __nv_bfloat16* src = ((c & 4) ? Blo : Bhi)
                + (size_t)(n0 + row) * K + k0 + (c & 3) * 8;
            CP_ASYNC16(dst, src);
        }
        CP_COMMIT();
    };

    stage(0);
    stage(1);
    for (int t = 0; t < T; ++t) {
        if (t < T - 1) { CP_WAIT1(); } else { CP_WAIT0(); }
        FENCE_ASYNC_SHARED();
        __syncthreads();

        if (wid == 0 && elect_one()) {
            const uint32_t sbase = smb_u + (t % 3) * G_STAGE;
            uint64_t da = make_desc(sbase);
            uint64_t db = make_desc(sbase + TCG_OFF_B);
#pragma unroll
            for (int k = 0; k < 2; ++k)
#pragma unroll
                for (int m = 0; m < 2; ++m) {
                    uint32_t d = tmem + m * 256;
                    uint64_t ao = (uint64_t)(m * 1024);
                    bool first = (t == 0) && (k == 0);
                    mma_bf16_ss(d, da + ao + k * 2,     db + k * 2,     G_IDESC, !first);
                    mma_bf16_ss(d, da + ao + k * 2,     db + 4 + k * 2, G_IDESC, true);
                    mma_bf16_ss(d, da + ao + 4 + k * 2, db + k * 2,     G_IDESC, true);
                }
            TC_COMMIT(smb_u + G_MBAR + 8 * (t % 3));
        }

        if (t + 2 < T) {
            if (t >= 1)
                mbar_wait(smb_u + G_MBAR + 8 * ((t + 2) % 3),
                          (uint32_t)(((t - 1) / 3) & 1));
            stage(t + 2);
        }
    }
#pragma unroll
    for (int i = 0; i < 3; ++i) {
        int cnt = (T + 2 - i) / 3;
        if (cnt > 0) mbar_wait(smb_u + G_MBAR + 8 * i, (uint32_t)((cnt - 1) & 1));
    }
    TC_FENCE_AFTER();

    {
        const int half = wid >> 2;
        const int mloc = (wid & 3) * 32 + lane;
        float* base;
        int col, ld;
        if (n0 < nsplit) { base = C;  col = n0;          ld = ldc;  }
        else             { base = C2; col = n0 - nsplit; ld = ldc2; }
        float* crow = base + (size_t)(m0 + half * 128 + mloc) * ld + col;
        uint32_t ra[32], rb[32];
#pragma unroll
        for (int cp = 0; cp < 4; ++cp) {       // 2 loads per wait
            TC_LD_X32(ra, tmem + half * 256 + (2 * cp) * 32);
            TC_LD_X32(rb, tmem + half * 256 + (2 * cp + 1) * 32);
            TC_WAIT_LD();
#pragma unroll
            for (int i = 0; i < 8; ++i)
                *(float4*)(crow + (2 * cp) * 32 + 4 * i) = make_float4(
                    __uint_as_float(ra[4*i]), __uint_as_float(ra[4*i+1]),
                    __uint_as_float(ra[4*i+2]), __uint_as_float(ra[4*i+3]));
#pragma unroll
            for (int i = 0; i < 8; ++i)
                *(float4*)(crow + (2 * cp + 1) * 32 + 4 * i) = make_float4(
                    __uint_as_float(rb[4*i]), __uint_as_float(rb[4*i+1]),
                    __uint_as_float(rb[4*i+2]), __uint_as_float(rb[4*i+3]));
        }
    }
    __syncthreads();
    if (tid == 0) {
        MBAR_INVAL(smb_u + G_MBAR + 0);
        MBAR_INVAL(smb_u + G_MBAR + 8);
        MBAR_INVAL(smb_u + G_MBAR + 16);
    }
    __syncthreads();
    if (wid == 0) { TC_RELINQ(); TC_DEALLOC(tmem, 512); }
#endif
}

// ---------------------------------------------------------------------------
// tcgen05 attention (R8 core; epilogue batches 2 TMEM loads per wait).
// ---------------------------------------------------------------------------
#define AT_Q     0
#define AT_KP    131072
#define AT_V     196608
#define AT_MBAR  229376
#define AT_TPTR  229408
#define AT_DYN   (229440 + 1024)
#define IDESC_S  ((1u<<4)|(1u<<7)|(1u<<10)|(8u<<17)|(8u<<24))
#define IDESC_O  ((1u<<4)|(1u<<7)|(1u<<10)|(16u<<17)|(8u<<24))
#define SMAX_C   12.0f

__global__ __launch_bounds__(256, 1) void tc_attn(
    const __nv_bfloat16* __restrict__ qsh, const __nv_bfloat16* __restrict__ qsl,
    const __nv_bfloat16* __restrict__ ksh, const __nv_bfloat16* __restrict__ ksl,
    const __nv_bfloat16* __restrict__ vth, const __nv_bfloat16* __restrict__ vtl,
    __nv_bfloat16* __restrict__ ohi, __nv_bfloat16* __restrict__ olo)
{
#if TC_FEAT
    extern __shared__ char dsm[];
    char* smb = (char*)(((uintptr_t)dsm + 1023) & ~(uintptr_t)1023);
    const uint32_t smb_u = smem_u32(smb);
    const uint32_t mbar_s = smb_u + AT_MBAR;
    const uint32_t mbar_o = smb_u + AT_MBAR + 8;
    const int tid = threadIdx.x;
    const int wid = tid >> 5;
    const int q0 = (int)(gridDim.x - 1 - blockIdx.x) * 64;
    const int kvh = blockIdx.y;
    const int b = blockIdx.z;
    const int bk = b * KVH + kvh;

    if (wid == 0) TC_ALLOC(smb_u + AT_TPTR, 512);
    if (tid == 0) { MBAR_INIT(mbar_s, 1); MBAR_INIT(mbar_o, 1); }
    __syncthreads();
    uint32_t tmem;
    asm volatile("ld.shared.b32 %0, [%1];" : "=r"(tmem) : "r"(smb_u + AT_TPTR));
    const uint32_t tmS = tmem;
    const uint32_t tmO = tmem + 128;

#pragma unroll
    for (int r = 0; r < 32; ++r) {
        int u = tid + r * 256;
        int row = u >> 5, cc = u & 31;
        int s = cc >> 4, hh = (cc >> 3) & 1, c = cc & 7;
        uint32_t byte = (uint32_t)(((row >> 3) + (s * 2 + hh) * 32) * 1024 +
                                   (row & 7) * 128 + c * 16);
        int tok = b * Sn + q0 + (row & 63);
        int head = kvh * 4 + (row >> 6);
        const __nv_bfloat16* src = (s ? qsl : qsh)
            + (size_t)tok * DM + head * HD + hh * 64 + c * 8;
        CP_ASYNC16(smb_u + AT_Q + SMEM_SW128(byte), src);
    }
    CP_COMMIT();

    const int kc0 = (q0 >= WINDOW) ? (q0 - WINDOW) : 0;
    const int nch = (q0 - kc0) / 64 + 1;
    float l_i = 0.f;
    uint32_t ps = 0, po = 0;
    const int atom = wid >> 2;
    const int grow = tid;
    const int qi = q0 + (grow & 63);

    for (int ci = 0; ci < nch; ++ci) {
        const int kc = kc0 + ci * 64;
        if (ci > 0) { mbar_wait(mbar_o, po); po ^= 1; }

#pragma unroll
        for (int r = 0; r < 8; ++r) {
            int u = tid + r * 256;
            int key = u >> 5, cc = u & 31;
            int s = cc >> 4, hh = (cc >> 3) & 1, c = cc & 7;
            uint32_t byte = (uint32_t)(((key >> 3) + (s * 2 + hh) * 8) * 1024 +
                                       (key & 7) * 128 + c * 16);
            const __nv_bfloat16* src = (s ? ksl : ksh)
                + (size_t)(b * Sn + kc + key) * KVD + kvh * HD + hh * 64 + c * 8;
            CP_ASYNC16(smb_u + AT_KP + SMEM_SW128(byte), src);
        }
        CP_COMMIT();
#pragma unroll
        for (int r = 0; r < 8; ++r) {
            int u = tid + r * 256;
            int d = u >> 4, cc = u & 15;
            int s = cc >> 3, c = cc & 7;
            uint32_t byte = (uint32_t)(((d >> 3) + s * 16) * 1024 +
                                       (d & 7) * 128 + c * 16);
            const __nv_bfloat16* src = (s ? vtl : vth)
                + (size_t)bk * HD * Sn + (size_t)d * Sn + kc + c * 8;
            CP_ASYNC16(smb_u + AT_V + SMEM_SW128(byte), src);
        }
        CP_COMMIT();
        CP_WAIT1();
        FENCE_ASYNC_SHARED();
        __syncthreads();

        if (wid == 0 && elect_one()) {
            uint64_t dq = make_desc(smb_u + AT_Q);
            uint64_t dk = make_desc(smb_u + AT_KP);
#pragma unroll
            for (int m = 0; m < 2; ++m)
#pragma unroll
                for (int pat = 0; pat < 3; ++pat) {
                    int sa = (pat == 2), sb = (pat == 1);
#pragma unroll
                    for (int k = 0; k < 8; ++k) {
                        uint64_t qo = (uint64_t)(m * 1024 +
                                      (sa * 2 + (k >> 2)) * 2048 + (k & 3) * 2);
                        uint64_t ko = (uint64_t)((sb * 2 + (k >> 2)) * 512 + (k & 3) * 2);
                        mma_bf16_ss(tmS + m * 64, dq + qo, dk + ko, IDESC_S,
                                    !(pat == 0 && k == 0));
                    }
                }
            TC_COMMIT(mbar_s);
        }

        mbar_wait(mbar_s, ps);
        ps ^= 1;
        TC_FENCE_AFTER();
        uint32_t su[64];
        TC_LD_X32(su, tmS + atom * 64);
        TC_LD_X32(su + 32, tmS + atom * 64 + 32);
        TC_WAIT_LD();
        float l_add = 0.f;
#pragma unroll
        for (int c16 = 0; c16 < 8; ++c16) {
            uint32_t wh[4], wl[4];
#pragma unroll
            for (int e = 0; e < 4; ++e) {
                int i0 = c16 * 8 + e * 2;
                int j0 = kc + i0;
                float s0 = __uint_as_float(su[i0]);
                float s1 = __uint_as_float(su[i0 + 1]);
                float p0 = ((j0 <= qi) && (j0 > qi - WINDOW)) ? __expf(s0 - SMAX_C) : 0.f;
                float p1 = ((j0+1 <= qi) && (j0+1 > qi - WINDOW)) ? __expf(s1 - SMAX_C) : 0.f;
                l_add += p0 + p1;
                split2(p0, p1, wh[e], wl[e]);
            }
            uint32_t bh = (uint32_t)((grow >> 3) * 1024 + (grow & 7) * 128 + c16 * 16);
            uint32_t bl = bh + 32 * 1024;
            *(uint4*)(smb + AT_KP + SMEM_SW128(bh)) = make_uint4(wh[0], wh[1], wh[2], wh[3]);
            *(uint4*)(smb + AT_KP + SMEM_SW128(bl)) = make_uint4(wl[0], wl[1], wl[2], wl[3]);
        }
        l_i += l_add;
        CP_WAIT0();
        FENCE_ASYNC_SHARED();
        __syncthreads();

        if (wid == 0 && elect_one()) {
            uint64_t dp = make_desc(smb_u + AT_KP);
            uint64_t dv = make_desc(smb_u + AT_V);
#pragma unroll
            for (int m = 0; m < 2; ++m)
#pragma unroll
                for (int pat = 0; pat < 3; ++pat) {
                    int sp = (pat == 2), sv = (pat == 1);
#pragma unroll
                    for (int k = 0; k < 4; ++k) {
                        uint64_t pofs = (uint64_t)(m * 1024 + sp * 2048 + k * 2);
                        uint64_t vofs = (uint64_t)(sv * 1024 + k * 2);
                        mma_bf16_ss(tmO + m * 128, dp + pofs, dv + vofs, IDESC_O,
                                    !(ci == 0 && pat == 0 && k == 0));
                    }
                }
            TC_COMMIT(mbar_o);
        }
        __syncthreads();
    }

    mbar_wait(mbar_o, po);
    TC_FENCE_AFTER();

    {
        const float inv = 1.0f / l_i;
        const int tok = b * Sn + q0 + (grow & 63);
        const int head = kvh * 4 + (grow >> 6);
        __nv_bfloat16* bh = ohi + (size_t)tok * DM + head * HD;
        __nv_bfloat16* bl = olo + (size_t)tok * DM + head * HD;
        uint32_t va[32], vb[32];
#pragma unroll
        for (int cp = 0; cp < 2; ++cp) {       // 2 loads per wait
            TC_LD_X32(va, tmO + atom * 128 + (2 * cp) * 32);
            TC_LD_X32(vb, tmO + atom * 128 + (2 * cp + 1) * 32);
            TC_WAIT_LD();
#pragma unroll
            for (int half = 0; half < 2; ++half) {
                const uint32_t* ov = half ? vb : va;
                const int c = 2 * cp + half;
#pragma unroll
                for (int g = 0; g < 4; ++g) {
                    uint32_t ph[4], pl[4];
#pragma unroll
                    for (int e = 0; e < 4; ++e) {
                        float v0 = __uint_as_float(ov[g*8 + e*2]) * inv;
                        float v1 = __uint_as_float(ov[g*8 + e*2 + 1]) * inv;
                        split2(v0, v1, ph[e], pl[e]);
                    }
                    *(uint4*)(bh + c * 32 + g * 8) = make_uint4(ph[0], ph[1], ph[2], ph[3]);
                    *(uint4*)(bl + c * 32 + g * 8) = make_uint4(pl[0], pl[1], pl[2], pl[3]);
                }
            }
        }
    }
    __syncthreads();
    if (tid == 0) { MBAR_INVAL(mbar_s); MBAR_INVAL(mbar_o); }
    __syncthreads();
    if (wid == 0) { TC_RELINQ(); TC_DEALLOC(tmem, 512); }
#endif
}

// ---------------------------------------------------------------------------
// Pre-pass kernels (byte-identical to R13)
// ---------------------------------------------------------------------------
__global__ __launch_bounds__(256) void convert_split(
    const float* __restrict__ x, __nv_bfloat16* __restrict__ hi,
    __nv_bfloat16* __restrict__ lo, int n4)
{
    int i = blockIdx.x * 256 + threadIdx.x;
    if (i >= n4) return;
    float4 v = ((const float4*)x)[i];
    __nv_bfloat16 h[4], l[4];
    float vv[4] = {v.x, v.y, v.z, v.w};
#pragma unroll
    for (int j = 0; j < 4; ++j) {
        h[j] = __float2bfloat16_rn(vv[j]);
        l[j] = __float2bfloat16_rn(vv[j] - __bfloat162float(h[j]));
    }
    ((uint64_t*)hi)[i] = *(uint64_t*)h;
    ((uint64_t*)lo)[i] = *(uint64_t*)l;
}

__global__ __launch_bounds__(256) void transpose_split(
    const float* __restrict__ W, __nv_bfloat16* __restrict__ Thi,
    __nv_bfloat16* __restrict__ Tlo, int K, int N, int noff)
{
    __shared__ float tile[32][33];
    const int n0 = blockIdx.x * 32, k0 = blockIdx.y * 32;
    const int tx = threadIdx.x, ty = threadIdx.y;
#pragma unroll
    for (int i = 0; i < 32; i += 8)
        tile[ty + i][tx] = W[(size_t)(k0 + ty + i) * N + n0 + tx];
    __syncthreads();
#pragma unroll
    for (int i = 0; i < 32; i += 8) {
        float v = tile[tx][ty + i];
        __nv_bfloat16 h = __float2bfloat16_rn(v);
        size_t idx = (size_t)(noff + n0 + ty + i) * K + k0 + tx;
        Thi[idx] = h;
        Tlo[idx] = __float2bfloat16_rn(v - __bfloat162float(h));
    }
}

__global__ __launch_bounds__(256) void v_split_t(
    const float* __restrict__ kv, __nv_bfloat16* __restrict__ vth,
    __nv_bfloat16* __restrict__ vtl)
{
    __shared__ float tile[32][33];
    const int t0 = blockIdx.x * 32, d0 = blockIdx.y * 32;
    const int bkk = blockIdx.z;
    const int bb = bkk >> 3, kvh = bkk & 7;
    const int tx = threadIdx.x, ty = threadIdx.y;
#pragma unroll
    for (int i = 0; i < 32; i += 8)
        tile[ty + i][tx] = kv[(size_t)(bb * Sn + t0 + ty + i) * KVLD +
                              KVD + kvh * HD + d0 + tx];
    __syncthreads();
#pragma unroll
    for (int i = 0; i < 32; i += 8) {
        float x = tile[tx][ty + i];
        __nv_bfloat16 h = __float2bfloat16_rn(x);
        size_t idx = (size_t)bkk * HD * Sn + (size_t)(d0 + ty + i) * Sn + t0 + tx;
        vth[idx] = h;
        vtl[idx] = __float2bfloat16_rn(x - __bfloat162float(h));
    }
}

__global__ __launch_bounds__(256) void rope_split(
    const float* __restrict__ q, const float* __restrict__ kv,
    __nv_bfloat16* __restrict__ qsh, __nv_bfloat16* __restrict__ qsl,
    __nv_bfloat16* __restrict__ ksh, __nv_bfloat16* __restrict__ ksl,
    const int* __restrict__ pos_ids)
{
    const int tok = blockIdx.x;
    __shared__ float cs[64], sn[64];
    const int tid = threadIdx.x;
    const float pos = (float)pos_ids[tok];
    const float SCALE = 0.08838834764831845f;
    if (tid < 64) {
        float inv = powf(1.0e6f, -((float)tid) / 64.0f);
        sincosf(pos * inv, &sn[tid], &cs[tid]);
    }
    __syncthreads();
    for (int p = tid; p < (Hq + KVH) * 64; p += 256) {
        int head = p >> 6, i = p & 63;
        float c = cs[i], s = sn[i];
        if (head < Hq) {
            size_t base = (size_t)tok * DM + head * HD;
            float x1 = q[base + i], x2 = q[base + i + 64];
            float y1 = (x1 * c - x2 * s) * SCALE;
            float y2 = (x2 * c + x1 * s) * SCALE;
            __nv_bfloat16 h1 = __float2bfloat16_rn(y1);
            __nv_bfloat16 h2 = __float2bfloat16_rn(y2);
            qsh[base + i] = h1;
            qsh[base + i + 64] = h2;
            qsl[base + i] = __float2bfloat16_rn(y1 - __bfloat162float(h1));
            qsl[base + i + 64] = __float2bfloat16_rn(y2 - __bfloat162float(h2));
        } else {
            int kh = head - Hq;
            size_t sbase = (size_t)tok * KVLD + kh * HD;
            size_t dbase = (size_t)tok * KVD + kh * HD;
            float x1 = kv[sbase + i], x2 = kv[sbase + i + 64];
            float y1 = x1 * c - x2 * s;
            float y2 = x2 * c + x1 * s;
            __nv_bfloat16 h1 = __float2bfloat16_rn(y1);
            __nv_bfloat16 h2 = __float2bfloat16_rn(y2);
            ksh[dbase + i] = h1;
            ksh[dbase + i + 64] = h2;
            ksl[dbase + i] = __float2bfloat16_rn(y1 - __bfloat162float(h1));
            ksl[dbase + i + 64] = __float2bfloat16_rn(y2 - __bfloat162float(h2));
        }
    }
}

// ---------------------------------------------------------------------------
extern "C" void kernel_launch(void* const* d_in, const int* in_sizes, int n_in,
                              void* d_out, int out_size)
{
    const float* hidden = (const float*)d_in[0];
    const float* Wq = (const float*)d_in[1];
    const float* Wk = (const float*)d_in[2];
    const float* Wv = (const float*)d_in[3];
    const float* Wo = (const float*)d_in[4];
    const int* pos_ids = (const int*)d_in[8];
    float* out = (float*)d_out;

    float *qp, *kvp;
    __nv_bfloat16 *ahi, *alo, *wqkvh, *wqkvl, *woh, *wol;
    __nv_bfloat16 *qsh, *qsl, *ksh, *ksl, *vth, *vtl, *oh, *ol;
    cudaGetSymbolAddress((void**)&qp, g_q);
    cudaGetSymbolAddress((void**)&kvp, g_kv);
    cudaGetSymbolAddress((void**)&ahi, g_a_hi);
    cudaGetSymbolAddress((void**)&alo, g_a_lo);
    cudaGetSymbolAddress((void**)&wqkvh, g_wqkv_hi);
    cudaGetSymbolAddress((void**)&wqkvl, g_wqkv_lo);
    cudaGetSymbolAddress((void**)&woh, g_wo_hi);
    cudaGetSymbolAddress((void**)&wol, g_wo_lo);
    cudaGetSymbolAddress((void**)&qsh, g_qs_hi);
    cudaGetSymbolAddress((void**)&qsl, g_qs_lo);
    cudaGetSymbolAddress((void**)&ksh, g_ks_hi);
    cudaGetSymbolAddress((void**)&ksl, g_ks_lo);
    cudaGetSymbolAddress((void**)&vth, g_vt_hi);
    cudaGetSymbolAddress((void**)&vtl, g_vt_lo);
    cudaGetSymbolAddress((void**)&oh, g_o_hi);
    cudaGetSymbolAddress((void**)&ol, g_o_lo);

    cudaFuncSetAttribute(tc_gemm, cudaFuncAttributeMaxDynamicSharedMemorySize, G_DYN);
    cudaFuncSetAttribute(tc_attn, cudaFuncAttributeMaxDynamicSharedMemorySize, AT_DYN);

    // pre-pass
    convert_split<<<(NTOK * DM / 4) / 256, 256>>>(hidden, ahi, alo, NTOK * DM / 4);
    transpose_split<<<dim3(DM / 32, DM / 32), dim3(32, 8)>>>(Wq, wqkvh, wqkvl, DM, DM, 0);
    transpose_split<<<dim3(KVD / 32, DM / 32), dim3(32, 8)>>>(Wk, wqkvh, wqkvl, DM, KVD, DM);
    transpose_split<<<dim3(KVD / 32, DM / 32), dim3(32, 8)>>>(Wv, wqkvh, wqkvl, DM, KVD, DM + KVD);
    transpose_split<<<dim3(DM / 32, DM / 32), dim3(32, 8)>>>(Wo, woh, wol, DM, DM, 0);

    // merged QKV projection: N=6144, 384 CTAs; Q -> g_q, K|V -> g_kv
    tc_gemm<<<dim3(NQKV / 256, NTOK / 256), 256, G_DYN>>>(
        ahi, alo, wqkvh, wqkvl, qp, kvp, DM, KVLD, DM, DM);

    // rope + attention operand prep
    rope_split<<<NTOK, 256>>>(qp, kvp, qsh, qsl, ksh, ksl, pos_ids);
    v_split_t<<<dim3(Sn / 32, HD / 32, Bn * KVH), dim3(32, 8)>>>(kvp, vth, vtl);

    // attention
    tc_attn<<<dim3(Sn / 64, KVH, Bn), 256, AT_DYN>>>(
        qsh, qsl, ksh, ksl, vth, vtl, oh, ol);

    // output projection
    tc_gemm<<<dim3(DM / 256, NTOK / 256), 256, G_DYN>>>(
        oh, ol, woh, wol, out, out, DM, DM, DM, DM);
}

// round 17
// speedup vs baseline: 1.6178x; 1.0027x over previous
#include <cuda_runtime.h>
#include <cuda_bf16.h>
#include <math.h>
#include <stdint.h>

#define Hq 32
#define KVH 8
#define HD 128
#define Bn 4
#define Sn 1024
#define DM 4096
#define KVD 1024
#define NTOK (Bn*Sn)
#define WINDOW 512
#define NQKV (DM + 2*KVD)    // 6144
#define KVLD (2*KVD)         // 2048

#if defined(__CUDA_ARCH_FEAT_SM103_ALL) || defined(__CUDA_ARCH_FEAT_SM100_ALL)
#define TC_FEAT 1
#else
#define TC_FEAT 0
#endif

// Scratch
__device__ float g_q[NTOK * DM];
__device__ float g_kv[NTOK * KVLD];               // [tok][K 0..1023 | V 1024..2047]
__device__ __nv_bfloat16 g_a_hi[NTOK * DM];
__device__ __nv_bfloat16 g_a_lo[NTOK * DM];
__device__ __nv_bfloat16 g_wqkv_hi[NQKV * DM];    // rows: Wq^T | Wk^T | Wv^T (K-major)
__device__ __nv_bfloat16 g_wqkv_lo[NQKV * DM];
__device__ __nv_bfloat16 g_wo_hi[DM * DM];
__device__ __nv_bfloat16 g_wo_lo[DM * DM];
__device__ __nv_bfloat16 g_qs_hi[NTOK * DM];
__device__ __nv_bfloat16 g_qs_lo[NTOK * DM];
__device__ __nv_bfloat16 g_ks_hi[NTOK * KVD];
__device__ __nv_bfloat16 g_ks_lo[NTOK * KVD];
__device__ __nv_bfloat16 g_vt_hi[NTOK * KVD];
__device__ __nv_bfloat16 g_vt_lo[NTOK * KVD];
__device__ __nv_bfloat16 g_o_hi[NTOK * DM];
__device__ __nv_bfloat16 g_o_lo[NTOK * DM];

__device__ __forceinline__ uint32_t smem_u32(const void* p) {
    uint32_t a;
    asm("{ .reg .u64 t; cvta.to.shared.u64 t, %1; cvt.u32.u64 %0, t; }"
        : "=r"(a) : "l"(p));
    return a;
}
__device__ __forceinline__ uint32_t elect_one() {
    uint32_t pred;
    asm volatile("{\n .reg .pred p;\n elect.sync _|p, 0xFFFFFFFF;\n"
                 " selp.b32 %0, 1, 0, p;\n}" : "=r"(pred));
    return pred;
}
#define SMEM_SW128(off) ((off) ^ (((off) >> 3) & 0x70))
static constexpr uint64_t DESC_BASE_SW128 =
    (uint64_t(2) << 61) | (uint64_t(1) << 46) | (uint64_t(64) << 32) |
    (uint64_t(1) << 16);
__device__ __forceinline__ uint64_t make_desc(uint32_t addr) {
    return DESC_BASE_SW128 | ((uint64_t)(addr >> 4) & 0x3FFF);
}
#define MBAR_INIT(a, n) \
    asm volatile("mbarrier.init.shared.b64 [%0], %1;" :: "r"(a), "r"(n) : "memory")
#define MBAR_INVAL(a) \
    asm volatile("mbarrier.inval.shared.b64 [%0];" :: "r"(a) : "memory")
__device__ __forceinline__ void mbar_wait(uint32_t mbar, uint32_t parity) {
    uint32_t done;
    asm volatile("{\n\t.reg .pred p;\n\t"
        "mbarrier.try_wait.parity.acquire.cta.shared::cta.b64 p, [%1], %2;\n\t"
        "selp.b32 %0, 1, 0, p;\n\t}" : "=r"(done) : "r"(mbar), "r"(parity) : "memory");
    while (!done) {
        asm volatile("{\n\t.reg .pred p;\n\t"
            "mbarrier.try_wait.parity.acquire.cta.shared::cta.b64 p, [%1], %2, 0x989680;\n\t"
            "selp.b32 %0, 1, 0, p;\n\t}" : "=r"(done) : "r"(mbar), "r"(parity) : "memory");
    }
}
#define CP_ASYNC16(dst, src) \
    asm volatile("cp.async.cg.shared.global [%0], [%1], 16;" :: "r"(dst), "l"(src))
#define CP_COMMIT() asm volatile("cp.async.commit_group;" ::: "memory")
#define CP_WAIT0()  asm volatile("cp.async.wait_group 0;" ::: "memory")
#define CP_WAIT1()  asm volatile("cp.async.wait_group 1;" ::: "memory")

#if TC_FEAT
__device__ __forceinline__ void mma_bf16_ss(
    uint32_t d_tmem, uint64_t a_desc, uint64_t b_desc, uint32_t idesc, bool acc)
{
    uint32_t en = acc ? 1u : 0u;
    asm volatile(
        "{\n\t.reg .pred p;\n\tsetp.ne.u32 p, %4, 0;\n\t"
        "tcgen05.mma.cta_group::1.kind::f16 [%0], %1, %2, %3, {%5,%5,%5,%5}, p;\n\t}"
        :: "r"(d_tmem), "l"(a_desc), "l"(b_desc), "r"(idesc), "r"(en), "r"(0u)
        : "memory");
}
#define TC_ALLOC(a, n) \
    asm volatile("tcgen05.alloc.cta_group::1.sync.aligned.shared::cta.b32 [%0], %1;" \
                 :: "r"(a), "r"((uint32_t)(n)) : "memory")
#define TC_DEALLOC(t, n) \
    asm volatile("tcgen05.dealloc.cta_group::1.sync.aligned.b32 %0, %1;" \
                 :: "r"(t), "r"((uint32_t)(n)))
#define TC_RELINQ() \
    asm volatile("tcgen05.relinquish_alloc_permit.cta_group::1.sync.aligned;")
#define TC_COMMIT(m) \
    asm volatile("tcgen05.commit.cta_group::1.mbarrier::arrive::one.shared::cluster.b64 [%0];" \
                 :: "r"(m) : "memory")
#define TC_FENCE_AFTER() asm volatile("tcgen05.fence::after_thread_sync;" ::: "memory")
#define FENCE_ASYNC_SHARED() asm volatile("fence.proxy.async.shared::cta;" ::: "memory")
#define TC_LD_X32(r, addr) \
    asm volatile("tcgen05.ld.sync.aligned.32x32b.x32.b32 " \
        "{%0,%1,%2,%3,%4,%5,%6,%7,%8,%9,%10,%11,%12,%13,%14,%15," \
        "%16,%17,%18,%19,%20,%21,%22,%23,%24,%25,%26,%27,%28,%29,%30,%31}, [%32];" \
        : "=r"((r)[0]), "=r"((r)[1]), "=r"((r)[2]), "=r"((r)[3]), \
          "=r"((r)[4]), "=r"((r)[5]), "=r"((r)[6]), "=r"((r)[7]), \
          "=r"((r)[8]), "=r"((r)[9]), "=r"((r)[10]), "=r"((r)[11]), \
          "=r"((r)[12]), "=r"((r)[13]), "=r"((r)[14]), "=r"((r)[15]), \
          "=r"((r)[16]), "=r"((r)[17]), "=r"((r)[18]), "=r"((r)[19]), \
          "=r"((r)[20]), "=r"((r)[21]), "=r"((r)[22]), "=r"((r)[23]), \
          "=r"((r)[24]), "=r"((r)[25]), "=r"((r)[26]), "=r"((r)[27]), \
          "=r"((r)[28]), "=r"((r)[29]), "=r"((r)[30]), "=r"((r)[31]) \
        : "r"(addr))
#define TC_WAIT_LD() asm volatile("tcgen05.wait::ld.sync.aligned;" ::: "memory")

__device__ __forceinline__ void split2(float a, float b, uint32_t& hw, uint32_t& lw) {
    __nv_bfloat16 ha = __float2bfloat16_rn(a);
    __nv_bfloat16 hb = __float2bfloat16_rn(b);
    __nv_bfloat16 la = __float2bfloat16_rn(a - __bfloat162float(ha));
    __nv_bfloat16 lb = __float2bfloat16_rn(b - __bfloat162float(hb));
    hw = ((uint32_t)__bfloat16_as_ushort(hb) << 16) | (uint32_t)__bfloat16_as_ushort(ha);
    lw = ((uint32_t)__bfloat16_as_ushort(lb) << 16) | (uint32_t)__bfloat16_as_ushort(la);
}
#endif

// ---------------------------------------------------------------------------
// tcgen05 GEMM (proven optimum): 256x256 tile, K-tile 32, 3-stage cp.async.
// ---------------------------------------------------------------------------
#define TCG_OFF_B 32768
#define G_STAGE   65536
#define G_MBAR    (3 * G_STAGE)
#define G_TPTR    (3 * G_STAGE + 32)
#define G_DYN     (3 * G_STAGE + 64 + 1024)
#define G_IDESC   ((1u<<4)|(1u<<7)|(1u<<10)|(32u<<17)|(8u<<24))   // N=256

__global__ __launch_bounds__(256, 1) void tc_gemm(
    const __nv_bfloat16* __restrict__ Ahi, const __nv_bfloat16* __restrict__ Alo,
    const __nv_bfloat16* __restrict__ Bhi, const __nv_bfloat16* __restrict__ Blo,
    float* __restrict__ C, float* __restrict__ C2,
    int ldc, int ldc2, int nsplit, int K)
{
#if TC_FEAT
    extern __shared__ char dsm[];
    char* smb = (char*)(((uintptr_t)dsm + 1023) & ~(uintptr_t)1023);
    const uint32_t smb_u = smem_u32(smb);
    const int tid = threadIdx.x;
    const int wid = tid >> 5;
    const int lane = tid & 31;
    const int m0 = blockIdx.y * 256;
    const int n0 = blockIdx.x * 256;

    if (wid == 0) TC_ALLOC(smb_u + G_TPTR, 512);
    if (tid == 0) {
        MBAR_INIT(smb_u + G_MBAR + 0, 1);
        MBAR_INIT(smb_u + G_MBAR + 8, 1);
        MBAR_INIT(smb_u + G_MBAR + 16, 1);
    }
    __syncthreads();
    uint32_t tmem;
    asm volatile("ld.shared.b32 %0, [%1];" : "=r"(tmem) : "r"(smb_u + G_TPTR));

    const int T = K >> 5;
    auto stage = [&](int t) {
        const uint32_t sbase = smb_u + (t % 3) * G_STAGE;
        const int k0 = t * 32;
#pragma unroll
        for (int r = 0; r < 8; ++r) {
            int i = tid + r * 256;
            int row = i >> 3, c = i & 7;
            uint32_t dst = sbase + SMEM_SW128((uint32_t)(row * 128 + c * 16));
            const __nv_bfloat16* src = ((c & 4) ? Alo : Ahi)
                + (size_t)(m0 + row) * K + k0 + (c & 3) * 8;
            CP_ASYNC16(dst, src);
        }
#pragma unroll
        for (int r = 0; r < 8; ++r) {
            int i = tid + r * 256;
            int row = i >> 3, c = i & 7;
            uint32_t dst = sbase + TCG_OFF_B + SMEM_SW128((uint32_t)(row * 128 + c * 16));
            const __nv_bfloat16* src = ((c & 4) ? Blo : Bhi)
                + (size_t)(n0 + row) * K + k0 + (c & 3) * 8;
            CP_ASYNC16(dst, src);
        }
        CP_COMMIT();
    };

    stage(0);
    stage(1);
    for (int t = 0; t < T; ++t) {
        if (t < T - 1) { CP_WAIT1(); } else { CP_WAIT0(); }
        FENCE_ASYNC_SHARED();
        __syncthreads();

        if (wid == 0 && elect_one()) {
            const uint32_t sbase = smb_u + (t % 3) * G_STAGE;
            uint64_t da = make_desc(sbase);
            uint64_t db = make_desc(sbase + TCG_OFF_B);
#pragma unroll
            for (int k = 0; k < 2; ++k)
#pragma unroll
                for (int m = 0; m < 2; ++m) {
                    uint32_t d = tmem + m * 256;
                    uint64_t ao = (uint64_t)(m * 1024);
                    bool first = (t == 0) && (k == 0);
                    mma_bf16_ss(d, da + ao + k * 2,     db + k * 2,     G_IDESC, !first);
                    mma_bf16_ss(d, da + ao + k * 2,     db + 4 + k * 2, G_IDESC, true);
                    mma_bf16_ss(d, da + ao + 4 + k * 2, db + k * 2,     G_IDESC, true);
                }
            TC_COMMIT(smb_u + G_MBAR + 8 * (t % 3));
        }

        if (t + 2 < T) {
            if (t >= 1)
                mbar_wait(smb_u + G_MBAR + 8 * ((t + 2) % 3),
                          (uint32_t)(((t - 1) / 3) & 1));
            stage(t + 2);
        }
    }
#pragma unroll
    for (int i = 0; i < 3; ++i) {
        int cnt = (T + 2 - i) / 3;
        if (cnt > 0) mbar_wait(smb_u + G_MBAR + 8 * i, (uint32_t)((cnt - 1) & 1));
    }
    TC_FENCE_AFTER();

    {
        const int half = wid >> 2;
        const int mloc = (wid & 3) * 32 + lane;
        float* base;
        int col, ld;
        if (n0 < nsplit) { base = C;  col = n0;          ld = ldc;  }
        else             { base = C2; col = n0 - nsplit; ld = ldc2; }
        float* crow = base + (size_t)(m0 + half * 128 + mloc) * ld + col;
        uint32_t ra[32], rb[32];
#pragma unroll
        for (int cp = 0; cp < 4; ++cp) {
            TC_LD_X32(ra, tmem + half * 256 + (2 * cp) * 32);
            TC_LD_X32(rb, tmem + half * 256 + (2 * cp + 1) * 32);
            TC_WAIT_LD();
#pragma unroll
            for (int i = 0; i < 8; ++i)
                *(float4*)(crow + (2 * cp) * 32 + 4 * i) = make_float4(
                    __uint_as_float(ra[4*i]), __uint_as_float(ra[4*i+1]),
                    __uint_as_float(ra[4*i+2]), __uint_as_float(ra[4*i+3]));
#pragma unroll
            for (int i = 0; i < 8; ++i)
                *(float4*)(crow + (2 * cp + 1) * 32 + 4 * i) = make_float4(
                    __uint_as_float(rb[4*i]), __uint_as_float(rb[4*i+1]),
                    __uint_as_float(rb[4*i+2]), __uint_as_float(rb[4*i+3]));
        }
    }
    __syncthreads();
    if (tid == 0) {
        MBAR_INVAL(smb_u + G_MBAR + 0);
        MBAR_INVAL(smb_u + G_MBAR + 8);
        MBAR_INVAL(smb_u + G_MBAR + 16);
    }
    __syncthreads();
    if (wid == 0) { TC_RELINQ(); TC_DEALLOC(tmem, 512); }
#endif
}

// ---------------------------------------------------------------------------
// tcgen05 attention (proven optimum).
// ---------------------------------------------------------------------------
#define AT_Q     0
#define AT_KP    131072
#define AT_V     196608
#define AT_MBAR  229376
#define AT_TPTR  229408
#define AT_DYN   (229440 + 1024)
#define IDESC_S  ((1u<<4)|(1u<<7)|(1u<<10)|(8u<<17)|(8u<<24))
#define IDESC_O  ((1u<<4)|(1u<<7)|(1u<<10)|(16u<<17)|(8u<<24))
#define SMAX_C   12.0f

__global__ __launch_bounds__(256, 1) void tc_attn(
    const __nv_bfloat16* __restrict__ qsh, const __nv_bfloat16* __restrict__ qsl,
    const __nv_bfloat16* __restrict__ ksh, const __nv_bfloat16* __restrict__ ksl,
    const __nv_bfloat16* __restrict__ vth, const __nv_bfloat16* __restrict__ vtl,
    __nv_bfloat16* __restrict__ ohi, __nv_bfloat16* __restrict__ olo)
{
#if TC_FEAT
    extern __shared__ char dsm[];
    char* smb = (char*)(((uintptr_t)dsm + 1023) & ~(uintptr_t)1023);
    const uint32_t smb_u = smem_u32(smb);
    const uint32_t mbar_s = smb_u + AT_MBAR;
    const uint32_t mbar_o = smb_u + AT_MBAR + 8;
    const int tid = threadIdx.x;
    const int wid = tid >> 5;
    const int q0 = (int)(gridDim.x - 1 - blockIdx.x) * 64;
    const int kvh = blockIdx.y;
    const int b = blockIdx.z;
    const int bk = b * KVH + kvh;

    if (wid == 0) TC_ALLOC(smb_u + AT_TPTR, 512);
    if (tid == 0) { MBAR_INIT(mbar_s, 1); MBAR_INIT(mbar_o, 1); }
    __syncthreads();
    uint32_t tmem;
    asm volatile("ld.shared.b32 %0, [%1];" : "=r"(tmem) : "r"(smb_u + AT_TPTR));
    const uint32_t tmS = tmem;
    const uint32_t tmO = tmem + 128;

#pragma unroll
    for (int r = 0; r < 32; ++r) {
        int u = tid + r * 256;
        int row = u >> 5, cc = u & 31;
        int s = cc >> 4, hh = (cc >> 3) & 1, c = cc & 7;
        uint32_t byte = (uint32_t)(((row >> 3) + (s * 2 + hh) * 32) * 1024 +
                                   (row & 7) * 128 + c * 16);
        int tok = b * Sn + q0 + (row & 63);
        int head = kvh * 4 + (row >> 6);
        const __nv_bfloat16* src = (s ? qsl : qsh)
            + (size_t)tok * DM + head * HD + hh * 64 + c * 8;
        CP_ASYNC16(smb_u + AT_Q + SMEM_SW128(byte), src);
    }
    CP_COMMIT();

    const int kc0 = (q0 >= WINDOW) ? (q0 - WINDOW) : 0;
    const int nch = (q0 - kc0) / 64 + 1;
    float l_i = 0.f;
    uint32_t ps = 0, po = 0;
    const int atom = wid >> 2;
    const int grow = tid;
    const int qi = q0 + (grow & 63);

    for (int ci = 0; ci < nch; ++ci) {
        const int kc = kc0 + ci * 64;
        if (ci > 0) { mbar_wait(mbar_o, po); po ^= 1; }

#pragma unroll
        for (int r = 0; r < 8; ++r) {
            int u = tid + r * 256;
            int key = u >> 5, cc = u & 31;
            int s = cc >> 4, hh = (cc >> 3) & 1, c = cc & 7;
            uint32_t byte = (uint32_t)(((key >> 3) + (s * 2 + hh) * 8) * 1024 +
                                       (key & 7) * 128 + c * 16);
            const __nv_bfloat16* src = (s ? ksl : ksh)
                + (size_t)(b * Sn + kc + key) * KVD + kvh * HD + hh * 64 + c * 8;
            CP_ASYNC16(smb_u + AT_KP + SMEM_SW128(byte), src);
        }
        CP_COMMIT();
#pragma unroll
        for (int r = 0; r < 8; ++r) {
            int u = tid + r * 256;
            int d = u >> 4, cc = u & 15;
            int s = cc >> 3, c = cc & 7;
            uint32_t byte = (uint32_t)(((d >> 3) + s * 16) * 1024 +
                                       (d & 7) * 128 + c * 16);
            const __nv_bfloat16* src = (s ? vtl : vth)
                + (size_t)bk * HD * Sn + (size_t)d * Sn + kc + c * 8;
            CP_ASYNC16(smb_u + AT_V + SMEM_SW128(byte), src);
        }
        CP_COMMIT();
        CP_WAIT1();
        FENCE_ASYNC_SHARED();
        __syncthreads();

        if (wid == 0 && elect_one()) {
            uint64_t dq = make_desc(smb_u + AT_Q);
            uint64_t dk = make_desc(smb_u + AT_KP);
#pragma unroll
            for (int m = 0; m < 2; ++m)
#pragma unroll
                for (int pat = 0; pat < 3; ++pat) {
                    int sa = (pat == 2), sb = (pat == 1);
#pragma unroll
                    for (int k = 0; k < 8; ++k) {
                        uint64_t qo = (uint64_t)(m * 1024 +
                                      (sa * 2 + (k >> 2)) * 2048 + (k & 3) * 2);
                        uint64_t ko = (uint64_t)((sb * 2 + (k >> 2)) * 512 + (k & 3) * 2);
                        mma_bf16_ss(tmS + m * 64, dq + qo, dk + ko, IDESC_S,
                                    !(pat == 0 && k == 0));
                    }
                }
            TC_COMMIT(mbar_s);
        }

        mbar_wait(mbar_s, ps);
        ps ^= 1;
        TC_FENCE_AFTER();
        uint32_t su[64];
        TC_LD_X32(su, tmS + atom * 64);
        TC_LD_X32(su + 32, tmS + atom * 64 + 32);
        TC_WAIT_LD();
        float l_add = 0.f;
#pragma unroll
        for (int c16 = 0; c16 < 8; ++c16) {
            uint32_t wh[4], wl[4];
#pragma unroll
            for (int e = 0; e < 4; ++e) {
                int i0 = c16 * 8 + e * 2;
                int j0 = kc + i0;
                float s0 = __uint_as_float(su[i0]);
                float s1 = __uint_as_float(su[i0 + 1]);
                float p0 = ((j0 <= qi) && (j0 > qi - WINDOW)) ? __expf(s0 - SMAX_C) : 0.f;
                float p1 = ((j0+1 <= qi) && (j0+1 > qi - WINDOW)) ? __expf(s1 - SMAX_C) : 0.f;
                l_add += p0 + p1;
                split2(p0, p1, wh[e], wl[e]);
            }
            uint32_t bh = (uint32_t)((grow >> 3) * 1024 + (grow & 7) * 128 + c16 * 16);
            uint32_t bl = bh + 32 * 1024;
            *(uint4*)(smb + AT_KP + SMEM_SW128(bh)) = make_uint4(wh[0], wh[1], wh[2], wh[3]);
            *(uint4*)(smb + AT_KP + SMEM_SW128(bl)) = make_uint4(wl[0], wl[1], wl[2], wl[3]);
        }
        l_i += l_add;
        CP_WAIT0();
        FENCE_ASYNC_SHARED();
        __syncthreads();

        if (wid == 0 && elect_one()) {
            uint64_t dp = make_desc(smb_u + AT_KP);
            uint64_t dv = make_desc(smb_u + AT_V);
#pragma unroll
            for (int m = 0; m < 2; ++m)
#pragma unroll
                for (int pat = 0; pat < 3; ++pat) {
                    int sp = (pat == 2), sv = (pat == 1);
#pragma unroll
                    for (int k = 0; k < 4; ++k) {
                        uint64_t pofs = (uint64_t)(m * 1024 + sp * 2048 + k * 2);
                        uint64_t vofs = (uint64_t)(sv * 1024 + k * 2);
                        mma_bf16_ss(tmO + m * 128, dp + pofs, dv + vofs, IDESC_O,
                                    !(ci == 0 && pat == 0 && k == 0));
                    }
                }
            TC_COMMIT(mbar_o);
        }
        __syncthreads();
    }

    mbar_wait(mbar_o, po);
    TC_FENCE_AFTER();

    {
        const float inv = 1.0f / l_i;
        const int tok = b * Sn + q0 + (grow & 63);
        const int head = kvh * 4 + (grow >> 6);
        __nv_bfloat16* bh = ohi + (size_t)tok * DM + head * HD;
        __nv_bfloat16* bl = olo + (size_t)tok * DM + head * HD;
        uint32_t va[32], vb[32];
#pragma unroll
        for (int cp = 0; cp < 2; ++cp) {
            TC_LD_X32(va, tmO + atom * 128 + (2 * cp) * 32);
            TC_LD_X32(vb, tmO + atom * 128 + (2 * cp + 1) * 32);
            TC_WAIT_LD();
#pragma unroll
            for (int half = 0; half < 2; ++half) {
                const uint32_t* ov = half ? vb : va;
                const int c = 2 * cp + half;
#pragma unroll
                for (int g = 0; g < 4; ++g) {
                    uint32_t ph[4], pl[4];
#pragma unroll
                    for (int e = 0; e < 4; ++e) {
                        float v0 = __uint_as_float(ov[g*8 + e*2]) * inv;
                        float v1 = __uint_as_float(ov[g*8 + e*2 + 1]) * inv;
                        split2(v0, v1, ph[e], pl[e]);
                    }
                    *(uint4*)(bh + c * 32 + g * 8) = make_uint4(ph[0], ph[1], ph[2], ph[3]);
                    *(uint4*)(bl + c * 32 + g * 8) = make_uint4(pl[0], pl[1], pl[2], pl[3]);
                }
            }
        }
    }
    __syncthreads();
    if (tid == 0) { MBAR_INVAL(mbar_s); MBAR_INVAL(mbar_o); }
    __syncthreads();
    if (wid == 0) { TC_RELINQ(); TC_DEALLOC(tmem, 512); }
#endif
}

// ---------------------------------------------------------------------------
// Pre-pass kernels
// ---------------------------------------------------------------------------
__global__ __launch_bounds__(256) void convert_split(
    const float* __restrict__ x, __nv_bfloat16* __restrict__ hi,
    __nv_bfloat16* __restrict__ lo, int n4)
{
    int i = blockIdx.x * 256 + threadIdx.x;
    if (i >= n4) return;
    float4 v = ((const float4*)x)[i];
    __nv_bfloat16 h[4], l[4];
    float vv[4] = {v.x, v.y, v.z, v.w};
#pragma unroll
    for (int j = 0; j < 4; ++j) {
        h[j] = __float2bfloat16_rn(vv[j]);
        l[j] = __float2bfloat16_rn(vv[j] - __bfloat162float(h[j]));
    }
    ((uint64_t*)hi)[i] = *(uint64_t*)h;
    ((uint64_t*)lo)[i] = *(uint64_t*)l;
}

// Fused weight transpose+split: all 4 weights in ONE launch.
// Segments (blocks): Wq 16384 | Wk 4096 | Wv 4096 | Wo 16384  = 40960 total.
__global__ __launch_bounds__(256) void transpose_split_all(
    const float* __restrict__ Wq, const float* __restrict__ Wk,
    const float* __restrict__ Wv, const float* __restrict__ Wo,
    __nv_bfloat16* __restrict__ qkvh, __nv_bfloat16* __restrict__ qkvl,
    __nv_bfloat16* __restrict__ woh, __nv_bfloat16* __restrict__ wol)
{
    __shared__ float tile[32][33];
    int bx = blockIdx.x;
    const float* W;
    __nv_bfloat16 *Th, *Tl;
    int N, noff;
    if (bx < 16384)      { W = Wq; Th = qkvh; Tl = qkvl; N = DM;  noff = 0; }
    else if (bx < 20480) { bx -= 16384; W = Wk; Th = qkvh; Tl = qkvl; N = KVD; noff = DM; }
    else if (bx < 24576) { bx -= 20480; W = Wv; Th = qkvh; Tl = qkvl; N = KVD; noff = DM + KVD; }
    else                 { bx -= 24576; W = Wo; Th = woh;  Tl = wol;  N = DM;  noff = 0; }
    const int nblocks = N >> 5;
    const int n0 = (bx % nblocks) * 32;
    const int k0 = (bx / nblocks) * 32;
    const int tx = threadIdx.x & 31, ty = threadIdx.x >> 5;
#pragma unroll
    for (int i = 0; i < 32; i += 8)
        tile[ty + i][tx] = W[(size_t)(k0 + ty + i) * N + n0 + tx];
    __syncthreads();
#pragma unroll
    for (int i = 0; i < 32; i += 8) {
        float v = tile[tx][ty + i];
        __nv_bfloat16 h = __float2bfloat16_rn(v);
        size_t idx = (size_t)(noff + n0 + ty + i) * DM + k0 + tx;
        Th[idx] = h;
        Tl[idx] = __float2bfloat16_rn(v - __bfloat162float(h));
    }
}

// Fused RoPE-split (y==0) + V transpose-split (y==1): one launch, grid 4096x2.
__global__ __launch_bounds__(256) void rope_vsplit(
    const float* __restrict__ q, const float* __restrict__ kv,
    __nv_bfloat16* __restrict__ qsh, __nv_bfloat16* __restrict__ qsl,
    __nv_bfloat16* __restrict__ ksh, __nv_bfloat16* __restrict__ ksl,
    __nv_bfloat16* __restrict__ vth, __nv_bfloat16* __restrict__ vtl,
    const int* __restrict__ pos_ids)
{
    const int tid = threadIdx.x;
    if (blockIdx.y == 0) {
        // --- RoPE + split (identical math to proven rope_split) ---
        const int tok = blockIdx.x;
        __shared__ float cs[64], sn[64];
        const float pos = (float)pos_ids[tok];
        const float SCALE = 0.08838834764831845f;
        if (tid < 64) {
            float inv = powf(1.0e6f, -((float)tid) / 64.0f);
            sincosf(pos * inv, &sn[tid], &cs[tid]);
        }
        __syncthreads();
        for (int p = tid; p < (Hq + KVH) * 64; p += 256) {
            int head = p >> 6, i = p & 63;
            float c = cs[i], s = sn[i];
            if (head < Hq) {
                size_t base = (size_t)tok * DM + head * HD;
                float x1 = q[base + i], x2 = q[base + i + 64];
                float y1 = (x1 * c - x2 * s) * SCALE;
                float y2 = (x2 * c + x1 * s) * SCALE;
                __nv_bfloat16 h1 = __float2bfloat16_rn(y1);
                __nv_bfloat16 h2 = __float2bfloat16_rn(y2);
                qsh[base + i] = h1;
                qsh[base + i + 64] = h2;
                qsl[base + i] = __float2bfloat16_rn(y1 - __bfloat162float(h1));
                qsl[base + i + 64] = __float2bfloat16_rn(y2 - __bfloat162float(h2));
            } else {
                int kh = head - Hq;
                size_t sbase = (size_t)tok * KVLD + kh * HD;
                size_t dbase = (size_t)tok * KVD + kh * HD;
                float x1 = kv[sbase + i], x2 = kv[sbase + i + 64];
                float y1 = x1 * c - x2 * s;
                float y2 = x2 * c + x1 * s;
                __nv_bfloat16 h1 = __float2bfloat16_rn(y1);
                __nv_bfloat16 h2 = __float2bfloat16_rn(y2);
                ksh[dbase + i] = h1;
                ksh[dbase + i + 64] = h2;
                ksl[dbase + i] = __float2bfloat16_rn(y1 - __bfloat162float(h1));
                ksl[dbase + i + 64] = __float2bfloat16_rn(y2 - __bfloat162float(h2));
            }
        }
    } else {
        // --- V transpose + split (identical math to proven v_split_t) ---
        __shared__ float tile[32][33];
        const int bx = blockIdx.x;           // 0..4095
        const int t0 = (bx & 31) * 32;       // token block
        const int d0 = ((bx >> 5) & 3) * 32; // dim block
        const int bkk = bx >> 7;             // b*KVH + kvh
        const int bb = bkk >> 3, kvh = bkk & 7;
        const int tx = tid & 31, ty = tid >> 5;
#pragma unroll
        for (int i = 0; i < 32; i += 8)
            tile[ty + i][tx] = kv[(size_t)(bb * Sn + t0 + ty + i) * KVLD +
                                  KVD + kvh * HD + d0 + tx];
        __syncthreads();
#pragma unroll
        for (int i = 0; i < 32; i += 8) {
            float x = tile[tx][ty + i];
            __nv_bfloat16 h = __float2bfloat16_rn(x);
            size_t idx = (size_t)bkk * HD * Sn + (size_t)(d0 + ty + i) * Sn + t0 + tx;
            vth[idx] = h;
            vtl[idx] = __float2bfloat16_rn(x - __bfloat162float(h));
        }
    }
}

// ---------------------------------------------------------------------------
extern "C" void kernel_launch(void* const* d_in, const int* in_sizes, int n_in,
                              void* d_out, int out_size)
{
    const float* hidden = (const float*)d_in[0];
    const float* Wq = (const float*)d_in[1];
    const float* Wk = (const float*)d_in[2];
    const float* Wv = (const float*)d_in[3];
    const float* Wo = (const float*)d_in[4];
    const int* pos_ids = (const int*)d_in[8];
    float* out = (float*)d_out;

    float *qp, *kvp;
    __nv_bfloat16 *ahi, *alo, *wqkvh, *wqkvl, *woh, *wol;
    __nv_bfloat16 *qsh, *qsl, *ksh, *ksl, *vth, *vtl, *oh, *ol;
    cudaGetSymbolAddress((void**)&qp, g_q);
    cudaGetSymbolAddress((void**)&kvp, g_kv);
    cudaGetSymbolAddress((void**)&ahi, g_a_hi);
    cudaGetSymbolAddress((void**)&alo, g_a_lo);
    cudaGetSymbolAddress((void**)&wqkvh, g_wqkv_hi);
    cudaGetSymbolAddress((void**)&wqkvl, g_wqkv_lo);
    cudaGetSymbolAddress((void**)&woh, g_wo_hi);
    cudaGetSymbolAddress((void**)&wol, g_wo_lo);
    cudaGetSymbolAddress((void**)&qsh, g_qs_hi);
    cudaGetSymbolAddress((void**)&qsl, g_qs_lo);
    cudaGetSymbolAddress((void**)&ksh, g_ks_hi);
    cudaGetSymbolAddress((void**)&ksl, g_ks_lo);
    cudaGetSymbolAddress((void**)&vth, g_vt_hi);
    cudaGetSymbolAddress((void**)&vtl, g_vt_lo);
    cudaGetSymbolAddress((void**)&oh, g_o_hi);
    cudaGetSymbolAddress((void**)&ol, g_o_lo);

    cudaFuncSetAttribute(tc_gemm, cudaFuncAttributeMaxDynamicSharedMemorySize, G_DYN);
    cudaFuncSetAttribute(tc_attn, cudaFuncAttributeMaxDynamicSharedMemorySize, AT_DYN);

    // pre-pass (2 launches instead of 5)
    convert_split<<<(NTOK * DM / 4) / 256, 256>>>(hidden, ahi, alo, NTOK * DM / 4);
    transpose_split_all<<<40960, 256>>>(Wq, Wk, Wv, Wo, wqkvh, wqkvl, woh, wol);

    // merged QKV projection: N=6144, 384 CTAs; Q -> g_q, K|V -> g_kv
    tc_gemm<<<dim3(NQKV / 256, NTOK / 256), 256, G_DYN>>>(
        ahi, alo, wqkvh, wqkvl, qp, kvp, DM, KVLD, DM, DM);

    // fused rope + V transpose (1 launch instead of 2)
    rope_vsplit<<<dim3(NTOK, 2), 256>>>(qp, kvp, qsh, qsl, ksh, ksl, vth, vtl, pos_ids);

    // attention
    tc_attn<<<dim3(Sn / 64, KVH, Bn), 256, AT_DYN>>>(
        qsh, qsl, ksh, ksl, vth, vtl, oh, ol);

    // output projection
    tc_gemm<<<dim3(DM / 256, NTOK / 256), 256, G_DYN>>>(
        oh, ol, woh, wol, out, out, DM, DM, DM, DM);
}